// round 1
// baseline (speedup 1.0000x reference)
#include <cuda_runtime.h>

#define DM 1024
#define NH 16
#define DK 64
#define SEQ 2048
#define BATCH 2
#define MTOT (BATCH*SEQ)   // 4096

// Scratch (allocation-free rule: __device__ globals)
__device__ float g_q[BATCH*NH*SEQ*DK];
__device__ float g_k[BATCH*NH*SEQ*DK];
__device__ float g_v[BATCH*NH*SEQ*DK];
__device__ float g_ctx[MTOT*DM];

// ---------------------------------------------------------------------------
// GEMM: Y = X @ W^T + bias.  X:[M,1024], W:[1024,1024] (row-major, torch Linear).
// Tile 64x64, K-step 16, 256 threads, 4x4 micro-tile.
// headmajor=1: write Y into [B,H,S,DK] layout (n-tile == head).
// ---------------------------------------------------------------------------
__global__ void gemm_bias_kernel(const float* __restrict__ X,
                                 const float* __restrict__ W,
                                 const float* __restrict__ bias,
                                 float* __restrict__ Y,
                                 int headmajor)
{
    __shared__ float As[16*64];   // As[k][m]
    __shared__ float Bs[16*64];   // Bs[k][n]
    const int t  = threadIdx.x;
    const int tx = t & 15, ty = t >> 4;
    const int n0 = blockIdx.x * 64;
    const int m0 = blockIdx.y * 64;
    const int r  = t >> 2, qd = t & 3;

    float acc[4][4] = {};

    for (int kt = 0; kt < DM; kt += 16) {
        float4 xv = *(const float4*)&X[(size_t)(m0 + r) * DM + kt + qd * 4];
        float4 wv = *(const float4*)&W[(size_t)(n0 + r) * DM + kt + qd * 4];
        As[(qd*4+0)*64 + r] = xv.x;
        As[(qd*4+1)*64 + r] = xv.y;
        As[(qd*4+2)*64 + r] = xv.z;
        As[(qd*4+3)*64 + r] = xv.w;
        Bs[(qd*4+0)*64 + r] = wv.x;
        Bs[(qd*4+1)*64 + r] = wv.y;
        Bs[(qd*4+2)*64 + r] = wv.z;
        Bs[(qd*4+3)*64 + r] = wv.w;
        __syncthreads();
        #pragma unroll
        for (int k = 0; k < 16; k++) {
            float4 a = *(float4*)&As[k*64 + ty*4];
            float4 b = *(float4*)&Bs[k*64 + tx*4];
            acc[0][0] += a.x*b.x; acc[0][1] += a.x*b.y; acc[0][2] += a.x*b.z; acc[0][3] += a.x*b.w;
            acc[1][0] += a.y*b.x; acc[1][1] += a.y*b.y; acc[1][2] += a.y*b.z; acc[1][3] += a.y*b.w;
            acc[2][0] += a.z*b.x; acc[2][1] += a.z*b.y; acc[2][2] += a.z*b.z; acc[2][3] += a.z*b.w;
            acc[3][0] += a.w*b.x; acc[3][1] += a.w*b.y; acc[3][2] += a.w*b.z; acc[3][3] += a.w*b.w;
        }
        __syncthreads();
    }

    #pragma unroll
    for (int i = 0; i < 4; i++) {
        const int m = m0 + ty*4 + i;
        #pragma unroll
        for (int j = 0; j < 4; j++) {
            const int n = n0 + tx*4 + j;
            float y = acc[i][j] + bias[n];
            if (headmajor) {
                const int b_ = m >> 11;          // m / SEQ
                const int s_ = m & 2047;         // m % SEQ
                const int h_ = blockIdx.x;       // n-tile == head (64-wide)
                g_q[0]; // no-op keep symbol (removed by compiler)
                Y[(((size_t)b_ * NH + h_) * SEQ + s_) * DK + (tx*4 + j)] = y;
            } else {
                Y[(size_t)m * DM + n] = y;
            }
        }
    }
}

// ---------------------------------------------------------------------------
// Row L2-normalize 64-wide rows in place. One warp per row.
// ---------------------------------------------------------------------------
__global__ void rownorm_kernel(float* __restrict__ p)
{
    const int row  = blockIdx.x * 8 + (threadIdx.x >> 5);
    const int lane = threadIdx.x & 31;
    float* rp = p + (size_t)row * DK;
    float v0 = rp[lane];
    float v1 = rp[lane + 32];
    float ss = v0*v0 + v1*v1;
    #pragma unroll
    for (int o = 16; o > 0; o >>= 1)
        ss += __shfl_xor_sync(0xffffffffu, ss, o);
    const float inv = rsqrtf(ss + 1e-8f);
    rp[lane]      = v0 * inv;
    rp[lane + 32] = v1 * inv;
}

// ---------------------------------------------------------------------------
// Attention: per (b,h) and 64-query tile, stream 64-key tiles:
//   S = Qn Kn^T ; O += (S*S) V
// Block 256 threads, 4x4 micro-tiles for both MMAs. 48KB static smem.
// Ks buffer is reused to hold S^2 (transposed) for phase B.
// ---------------------------------------------------------------------------
__global__ void attn_kernel(const float* __restrict__ q,
                            const float* __restrict__ k,
                            const float* __restrict__ v,
                            float* __restrict__ ctx)
{
    __shared__ float Qs[64*64];   // Qs[d][row]
    __shared__ float Ks[64*64];   // Ks[d][col]  -> reused as Sst[col][row]
    __shared__ float Vs[64*64];   // Vs[kk][col]

    const int t  = threadIdx.x;
    const int tx = t & 15, ty = t >> 4;
    const int q0 = blockIdx.x * 64;
    const int bh = blockIdx.y;

    const float* qh = q + (size_t)bh * SEQ * DK;
    const float* kh = k + (size_t)bh * SEQ * DK;
    const float* vh = v + (size_t)bh * SEQ * DK;

    const int r = t >> 2, qd = t & 3;

    // Load Q tile transposed: Qs[d][r] = qh[(q0+r)*64 + d]
    #pragma unroll
    for (int j = 0; j < 4; j++) {
        const int d0 = qd*16 + j*4;
        float4 val = *(const float4*)&qh[(size_t)(q0 + r) * DK + d0];
        Qs[(d0+0)*64 + r] = val.x;
        Qs[(d0+1)*64 + r] = val.y;
        Qs[(d0+2)*64 + r] = val.z;
        Qs[(d0+3)*64 + r] = val.w;
    }

    float o[4][4] = {};

    for (int kt = 0; kt < SEQ; kt += 64) {
        __syncthreads();   // prev phase-B reads done; Qs visible on first iter

        // K tile transposed: Ks[d][c]
        #pragma unroll
        for (int j = 0; j < 4; j++) {
            const int d0 = qd*16 + j*4;
            float4 val = *(const float4*)&kh[(size_t)(kt + r) * DK + d0];
            Ks[(d0+0)*64 + r] = val.x;
            Ks[(d0+1)*64 + r] = val.y;
            Ks[(d0+2)*64 + r] = val.z;
            Ks[(d0+3)*64 + r] = val.w;
        }
        // V tile natural: contiguous copy
        #pragma unroll
        for (int j = 0; j < 4; j++) {
            const int idx = t + j * 256;
            *(float4*)&Vs[idx*4] = *(const float4*)&vh[(size_t)kt * DK + idx*4];
        }
        __syncthreads();

        // Phase A: S[r][c] = sum_d Qs[d][r]*Ks[d][c]
        float s_[4][4] = {};
        #pragma unroll 8
        for (int d = 0; d < 64; d++) {
            float4 a = *(float4*)&Qs[d*64 + ty*4];
            float4 b = *(float4*)&Ks[d*64 + tx*4];
            s_[0][0] += a.x*b.x; s_[0][1] += a.x*b.y; s_[0][2] += a.x*b.z; s_[0][3] += a.x*b.w;
            s_[1][0] += a.y*b.x; s_[1][1] += a.y*b.y; s_[1][2] += a.y*b.z; s_[1][3] += a.y*b.w;
            s_[2][0] += a.z*b.x; s_[2][1] += a.z*b.y; s_[2][2] += a.z*b.z; s_[2][3] += a.z*b.w;
            s_[3][0] += a.w*b.x; s_[3][1] += a.w*b.y; s_[3][2] += a.w*b.z; s_[3][3] += a.w*b.w;
        }
        __syncthreads();   // all Ks reads done before overwrite

        // Square and store transposed into Ks: Sst[c][r] = S[r][c]^2
        #pragma unroll
        for (int i = 0; i < 4; i++)
            #pragma unroll
            for (int j = 0; j < 4; j++)
                Ks[(tx*4 + j)*64 + (ty*4 + i)] = s_[i][j] * s_[i][j];
        __syncthreads();

        // Phase B: O[r][c2] += sum_kk Sst[kk][r] * Vs[kk][c2]
        #pragma unroll 8
        for (int kk = 0; kk < 64; kk++) {
            float4 a = *(float4*)&Ks[kk*64 + ty*4];
            float4 b = *(float4*)&Vs[kk*64 + tx*4];
            o[0][0] += a.x*b.x; o[0][1] += a.x*b.y; o[0][2] += a.x*b.z; o[0][3] += a.x*b.w;
            o[1][0] += a.y*b.x; o[1][1] += a.y*b.y; o[1][2] += a.y*b.z; o[1][3] += a.y*b.w;
            o[2][0] += a.z*b.x; o[2][1] += a.z*b.y; o[2][2] += a.z*b.z; o[2][3] += a.z*b.w;
            o[3][0] += a.w*b.x; o[3][1] += a.w*b.y; o[3][2] += a.w*b.z; o[3][3] += a.w*b.w;
        }
    }

    // Write ctx in [B,S,DM] layout for the output projection
    const int b_ = bh >> 4;
    const int h_ = bh & 15;
    #pragma unroll
    for (int i = 0; i < 4; i++) {
        const int s_ = q0 + ty*4 + i;
        #pragma unroll
        for (int j = 0; j < 4; j++) {
            ctx[((size_t)b_ * SEQ + s_) * DM + h_ * DK + tx*4 + j] = o[i][j];
        }
    }
}

// ---------------------------------------------------------------------------
extern "C" void kernel_launch(void* const* d_in, const int* in_sizes, int n_in,
                              void* d_out, int out_size)
{
    const float* Q    = (const float*)d_in[0];
    const float* K    = (const float*)d_in[1];
    const float* V    = (const float*)d_in[2];
    const float* Wq_w = (const float*)d_in[3];
    const float* Wq_b = (const float*)d_in[4];
    const float* Wk_w = (const float*)d_in[5];
    const float* Wk_b = (const float*)d_in[6];
    const float* Wv_w = (const float*)d_in[7];
    const float* Wv_b = (const float*)d_in[8];
    const float* Wo_w = (const float*)d_in[9];
    const float* Wo_b = (const float*)d_in[10];
    float* out = (float*)d_out;

    float *q, *k, *v, *ctx;
    cudaGetSymbolAddress((void**)&q,   g_q);
    cudaGetSymbolAddress((void**)&k,   g_k);
    cudaGetSymbolAddress((void**)&v,   g_v);
    cudaGetSymbolAddress((void**)&ctx, g_ctx);

    dim3 gemm_grid(DM / 64, MTOT / 64);   // (16, 64)
    dim3 blk(256);

    gemm_bias_kernel<<<gemm_grid, blk>>>(Q, Wq_w, Wq_b, q, 1);
    gemm_bias_kernel<<<gemm_grid, blk>>>(K, Wk_w, Wk_b, k, 1);
    gemm_bias_kernel<<<gemm_grid, blk>>>(V, Wv_w, Wv_b, v, 1);

    const int nrows = BATCH * NH * SEQ;   // 65536
    rownorm_kernel<<<nrows / 8, 256>>>(q);
    rownorm_kernel<<<nrows / 8, 256>>>(k);

    dim3 attn_grid(SEQ / 64, BATCH * NH); // (32, 32)
    attn_kernel<<<attn_grid, blk>>>(q, k, v, ctx);

    gemm_bias_kernel<<<gemm_grid, blk>>>(ctx, Wo_w, Wo_b, out, 0);
}

// round 3
// speedup vs baseline: 2.6753x; 2.6753x over previous
#include <cuda_runtime.h>
#include <cuda_bf16.h>
#include <stdint.h>

#define DM 1024
#define NH 16
#define DK 64
#define SEQ 2048
#define MTOT 4096
#define NBH 32
#define NX (MTOT*DM)   /* 4194304 */
#define NW (DM*DM)     /* 1048576 */
#define LDP 72         /* padded smem row stride (bf16 elems) for 64-wide tiles */
#define LDV 136        /* padded stride for 128-wide V tiles */

// scratch arena
__device__ __nv_bfloat16 g_buf[14ull*NX + 8ull*NW];

#define OFF_XQH 0ull
#define OFF_XQL (1ull*NX)
#define OFF_XKH (2ull*NX)
#define OFF_XKL (3ull*NX)
#define OFF_XVH (4ull*NX)
#define OFF_XVL (5ull*NX)
#define OFF_W   (6ull*NX)
#define OFF_QH  (OFF_W + 8ull*NW)
#define OFF_QL  (OFF_QH + 1ull*NX)
#define OFF_KH  (OFF_QH + 2ull*NX)
#define OFF_KL  (OFF_QH + 3ull*NX)
#define OFF_VH  (OFF_QH + 4ull*NX)   /* transposed [b,h,d,s] */
#define OFF_VL  (OFF_QH + 5ull*NX)
#define OFF_CH  (OFF_QH + 6ull*NX)
#define OFF_CL  (OFF_QH + 7ull*NX)

static __device__ __forceinline__ uint32_t smem_u32(const void* p) {
    uint32_t a;
    asm("{ .reg .u64 t; cvta.to.shared.u64 t, %1; cvt.u32.u64 %0, t; }" : "=r"(a) : "l"(p));
    return a;
}

#define MMA(C, A, B) asm volatile( \
    "mma.sync.aligned.m16n8k16.row.col.f32.bf16.bf16.f32 " \
    "{%0,%1,%2,%3}, {%4,%5,%6,%7}, {%8,%9}, {%0,%1,%2,%3};" \
    : "+f"((C)[0]), "+f"((C)[1]), "+f"((C)[2]), "+f"((C)[3]) \
    : "r"((A)[0]), "r"((A)[1]), "r"((A)[2]), "r"((A)[3]), \
      "r"((B)[0]), "r"((B)[1]))

#define LDM4(R, ADDR) asm volatile( \
    "ldmatrix.sync.aligned.m8n8.x4.shared.b16 {%0,%1,%2,%3}, [%4];" \
    : "=r"((R)[0]), "=r"((R)[1]), "=r"((R)[2]), "=r"((R)[3]) : "r"(ADDR))

static __device__ __forceinline__ void split2(float x0, float x1,
                                              uint32_t& hp, uint32_t& lp) {
    __nv_bfloat16 h0 = __float2bfloat16(x0), h1 = __float2bfloat16(x1);
    __nv_bfloat16 l0 = __float2bfloat16(x0 - __bfloat162float(h0));
    __nv_bfloat16 l1 = __float2bfloat16(x1 - __bfloat162float(h1));
    hp = (uint32_t)__bfloat16_as_ushort(h0) | ((uint32_t)__bfloat16_as_ushort(h1) << 16);
    lp = (uint32_t)__bfloat16_as_ushort(l0) | ((uint32_t)__bfloat16_as_ushort(l1) << 16);
}

// fp32 -> (hi, lo) bf16 split, 8 elems/thread
__global__ void split_kernel(const float4* __restrict__ src,
                             uint4* __restrict__ hi, uint4* __restrict__ lo, int nchunks)
{
    int i = blockIdx.x * blockDim.x + threadIdx.x;
    if (i >= nchunks) return;
    float4 a = src[i*2], b = src[i*2+1];
    float v[8] = {a.x, a.y, a.z, a.w, b.x, b.y, b.z, b.w};
    uint4 H, L;
    split2(v[0], v[1], H.x, L.x);
    split2(v[2], v[3], H.y, L.y);
    split2(v[4], v[5], H.z, L.z);
    split2(v[6], v[7], H.w, L.w);
    hi[i] = H;
    lo[i] = L;
}

// ---------------------------------------------------------------------------
// GEMM: Y = A @ W^T + bias. CTA 128x128, k-step 64, 8 warps (warp tile 32x64).
// bf16 split-3 via mma.sync m16n8k16.
// mode 0: fp32 [M,DM] out
// mode 1: head-major TRANSPOSED split out [b,h,d,s]  (V)
// mode 3: head-major split out [b,h,s,d] with fused L2 rownorm  (Q,K)
// ---------------------------------------------------------------------------
#define GEMM_SMEM (4*128*LDP*2)
__global__ void __launch_bounds__(256) gemm_mma(
    const __nv_bfloat16* __restrict__ Ah, const __nv_bfloat16* __restrict__ Al,
    const __nv_bfloat16* __restrict__ Wh, const __nv_bfloat16* __restrict__ Wl,
    const float* __restrict__ bias, float* __restrict__ Yf,
    __nv_bfloat16* __restrict__ Yh, __nv_bfloat16* __restrict__ Yl, int mode)
{
    extern __shared__ char sm[];
    char* pA[2] = { sm,              sm + 128*LDP*2 };
    char* pB[2] = { sm + 2*128*LDP*2, sm + 3*128*LDP*2 };
    const uint32_t uA[2] = { smem_u32(pA[0]), smem_u32(pA[1]) };
    const uint32_t uB[2] = { smem_u32(pB[0]), smem_u32(pB[1]) };

    const int t = threadIdx.x, lane = t & 31, w = t >> 5;
    const int wm = w & 3, wn = w >> 2;
    const int n0 = blockIdx.x * 128, m0 = blockIdx.y * 128;

    const __nv_bfloat16* Ap[2] = { Ah, Al };
    const __nv_bfloat16* Wp[2] = { Wh, Wl };

    float acc[2][8][4];
    #pragma unroll
    for (int i = 0; i < 2; i++)
        #pragma unroll
        for (int j = 0; j < 8; j++)
            #pragma unroll
            for (int k = 0; k < 4; k++) acc[i][j][k] = 0.f;

    const int aRow = wm*32 + (lane & 15);
    const int aCol = (lane >> 4) * 8;
    const int bRow = wn*64 + (lane & 7) + ((lane >> 4) << 3);
    const int bCol = ((lane >> 3) & 1) * 8;

    for (int kt = 0; kt < DM; kt += 64) {
        #pragma unroll
        for (int part = 0; part < 2; part++) {
            #pragma unroll
            for (int i = 0; i < 4; i++) {
                int c = t + i * 256;
                int row = c >> 3, q = c & 7;
                uint4 va = *(const uint4*)(Ap[part] + (size_t)(m0 + row) * DM + kt + q * 8);
                *(uint4*)(pA[part] + (row * LDP + q * 8) * 2) = va;
                uint4 vb = *(const uint4*)(Wp[part] + (size_t)(n0 + row) * DM + kt + q * 8);
                *(uint4*)(pB[part] + (row * LDP + q * 8) * 2) = vb;
            }
        }
        __syncthreads();
        #pragma unroll
        for (int ks = 0; ks < 4; ks++) {
            uint32_t aF[2][2][4];
            #pragma unroll
            for (int part = 0; part < 2; part++)
                #pragma unroll
                for (int mt = 0; mt < 2; mt++)
                    LDM4(aF[part][mt],
                         uA[part] + ((aRow + mt*16) * LDP + ks*16 + aCol) * 2);
            uint32_t bF[2][8][2];
            #pragma unroll
            for (int part = 0; part < 2; part++)
                #pragma unroll
                for (int nt2 = 0; nt2 < 4; nt2++) {
                    uint32_t r[4];
                    LDM4(r, uB[part] + ((bRow + nt2*16) * LDP + ks*16 + bCol) * 2);
                    bF[part][nt2*2  ][0] = r[0]; bF[part][nt2*2  ][1] = r[1];
                    bF[part][nt2*2+1][0] = r[2]; bF[part][nt2*2+1][1] = r[3];
                }
            #pragma unroll
            for (int mt = 0; mt < 2; mt++)
                #pragma unroll
                for (int nt = 0; nt < 8; nt++) {
                    MMA(acc[mt][nt], aF[0][mt], bF[0][nt]);
                    MMA(acc[mt][nt], aF[0][mt], bF[1][nt]);
                    MMA(acc[mt][nt], aF[1][mt], bF[0][nt]);
                }
        }
        __syncthreads();
    }

    // ---- epilogue ----
    const int g = lane >> 2, tig = lane & 3;
    #pragma unroll
    for (int mt = 0; mt < 2; mt++) {
        const int r0 = m0 + wm*32 + mt*16 + g;
        float v[2][8][2];
        #pragma unroll
        for (int nt = 0; nt < 8; nt++) {
            int col = n0 + wn*64 + nt*8 + tig*2;
            float b0v = bias[col], b1v = bias[col + 1];
            v[0][nt][0] = acc[mt][nt][0] + b0v;
            v[0][nt][1] = acc[mt][nt][1] + b1v;
            v[1][nt][0] = acc[mt][nt][2] + b0v;
            v[1][nt][1] = acc[mt][nt][3] + b1v;
        }
        if (mode == 0) {
            #pragma unroll
            for (int rr = 0; rr < 2; rr++) {
                int r = r0 + rr*8;
                #pragma unroll
                for (int nt = 0; nt < 8; nt++) {
                    int col = n0 + wn*64 + nt*8 + tig*2;
                    *(float2*)(Yf + (size_t)r * DM + col) =
                        make_float2(v[rr][nt][0], v[rr][nt][1]);
                }
            }
        } else {
            if (mode == 3) {
                #pragma unroll
                for (int rr = 0; rr < 2; rr++) {
                    float ss = 0.f;
                    #pragma unroll
                    for (int nt = 0; nt < 8; nt++)
                        ss += v[rr][nt][0]*v[rr][nt][0] + v[rr][nt][1]*v[rr][nt][1];
                    ss += __shfl_xor_sync(0xffffffffu, ss, 1);
                    ss += __shfl_xor_sync(0xffffffffu, ss, 2);
                    float inv = rsqrtf(ss + 1e-8f);
                    #pragma unroll
                    for (int nt = 0; nt < 8; nt++) {
                        v[rr][nt][0] *= inv;
                        v[rr][nt][1] *= inv;
                    }
                }
            }
            const int h_ = (n0 >> 6) + wn;
            const int b_ = r0 >> 11;
            #pragma unroll
            for (int rr = 0; rr < 2; rr++) {
                const int s_ = (r0 + rr*8) & 2047;
                if (mode == 1) {
                    const size_t base = (size_t)(b_ * NH + h_) * DK;
                    #pragma unroll
                    for (int nt = 0; nt < 8; nt++) {
                        int d = nt*8 + tig*2;
                        float x0 = v[rr][nt][0], x1 = v[rr][nt][1];
                        __nv_bfloat16 h0 = __float2bfloat16(x0);
                        __nv_bfloat16 h1 = __float2bfloat16(x1);
                        Yh[(base + d    ) * SEQ + s_] = h0;
                        Yh[(base + d + 1) * SEQ + s_] = h1;
                        Yl[(base + d    ) * SEQ + s_] =
                            __float2bfloat16(x0 - __bfloat162float(h0));
                        Yl[(base + d + 1) * SEQ + s_] =
                            __float2bfloat16(x1 - __bfloat162float(h1));
                    }
                } else {
                    const size_t base = ((size_t)(b_ * NH + h_) * SEQ + s_) * DK;
                    #pragma unroll
                    for (int nt = 0; nt < 8; nt++) {
                        uint32_t hp, lp;
                        split2(v[rr][nt][0], v[rr][nt][1], hp, lp);
                        *(uint32_t*)(Yh + base + nt*8 + tig*2) = hp;
                        *(uint32_t*)(Yl + base + nt*8 + tig*2) = lp;
                    }
                }
            }
        }
    }
}

// ---------------------------------------------------------------------------
// Attention: CTA = (bh, 128-q tile), 8 warps x 16 q-rows. Stream 128-key tiles:
//   S = Qn Kn^T (mma, split-3) -> square + split in regs -> O += P V (mma, split-3)
// ---------------------------------------------------------------------------
#define ATTN_SMEM (4*128*LDP*2 + 2*64*LDV*2)
__global__ void __launch_bounds__(256) attn_mma(
    const __nv_bfloat16* __restrict__ qhp, const __nv_bfloat16* __restrict__ qlp,
    const __nv_bfloat16* __restrict__ khp, const __nv_bfloat16* __restrict__ klp,
    const __nv_bfloat16* __restrict__ vhp, const __nv_bfloat16* __restrict__ vlp,
    __nv_bfloat16* __restrict__ ch, __nv_bfloat16* __restrict__ cl)
{
    extern __shared__ char sm[];
    char* pQ[2] = { sm,                sm +   128*LDP*2 };
    char* pK[2] = { sm + 2*128*LDP*2,  sm + 3*128*LDP*2 };
    char* pV[2] = { sm + 4*128*LDP*2,  sm + 4*128*LDP*2 + 64*LDV*2 };
    const uint32_t uQ[2] = { smem_u32(pQ[0]), smem_u32(pQ[1]) };
    const uint32_t uK[2] = { smem_u32(pK[0]), smem_u32(pK[1]) };
    const uint32_t uV[2] = { smem_u32(pV[0]), smem_u32(pV[1]) };

    const int t = threadIdx.x, lane = t & 31, w = t >> 5;
    const int q0 = blockIdx.x * 128;
    const int bh = blockIdx.y;
    const size_t base = (size_t)bh * SEQ * DK;

    const __nv_bfloat16* Qsrc[2] = { qhp, qlp };
    const __nv_bfloat16* Ksrc[2] = { khp, klp };
    const __nv_bfloat16* Vsrc[2] = { vhp, vlp };

    // Q tile once
    #pragma unroll
    for (int part = 0; part < 2; part++)
        #pragma unroll
        for (int i = 0; i < 4; i++) {
            int c = t + i * 256;
            int row = c >> 3, q = c & 7;
            uint4 val = *(const uint4*)(Qsrc[part] + base + (size_t)(q0 + row) * DK + q * 8);
            *(uint4*)(pQ[part] + (row * LDP + q * 8) * 2) = val;
        }

    float o[8][4];
    #pragma unroll
    for (int i = 0; i < 8; i++)
        #pragma unroll
        for (int j = 0; j < 4; j++) o[i][j] = 0.f;

    const int aRow = w*16 + (lane & 15);
    const int aCol = (lane >> 4) * 8;
    const int bRowOff = (lane & 7) + ((lane >> 4) << 3);
    const int bCol = ((lane >> 3) & 1) * 8;

    for (int kt = 0; kt < SEQ; kt += 128) {
        // K tile [key][d]
        #pragma unroll
        for (int part = 0; part < 2; part++)
            #pragma unroll
            for (int i = 0; i < 4; i++) {
                int c = t + i * 256;
                int row = c >> 3, q = c & 7;
                uint4 val = *(const uint4*)(Ksrc[part] + base + (size_t)(kt + row) * DK + q * 8);
                *(uint4*)(pK[part] + (row * LDP + q * 8) * 2) = val;
            }
        // V tile [d][key] (global already transposed)
        #pragma unroll
        for (int part = 0; part < 2; part++)
            #pragma unroll
            for (int i = 0; i < 4; i++) {
                int c = t + i * 256;
                int d = c >> 4, q = c & 15;
                uint4 val = *(const uint4*)(Vsrc[part] + base + (size_t)d * SEQ + kt + q * 8);
                *(uint4*)(pV[part] + (d * LDV + q * 8) * 2) = val;
            }
        __syncthreads();

        // S = Qn Kn^T : 16 n8 tiles over 128 keys
        float s[16][4];
        #pragma unroll
        for (int i = 0; i < 16; i++)
            #pragma unroll
            for (int j = 0; j < 4; j++) s[i][j] = 0.f;

        #pragma unroll
        for (int ks = 0; ks < 4; ks++) {
            uint32_t aQ[2][4];
            #pragma unroll
            for (int part = 0; part < 2; part++)
                LDM4(aQ[part], uQ[part] + (aRow * LDP + ks*16 + aCol) * 2);
            #pragma unroll
            for (int half = 0; half < 2; half++) {
                uint32_t bK[2][8][2];
                #pragma unroll
                for (int part = 0; part < 2; part++)
                    #pragma unroll
                    for (int nt2 = 0; nt2 < 4; nt2++) {
                        uint32_t r[4];
                        LDM4(r, uK[part] +
                             ((half*64 + nt2*16 + bRowOff) * LDP + ks*16 + bCol) * 2);
                        bK[part][nt2*2  ][0] = r[0]; bK[part][nt2*2  ][1] = r[1];
                        bK[part][nt2*2+1][0] = r[2]; bK[part][nt2*2+1][1] = r[3];
                    }
                #pragma unroll
                for (int nt = 0; nt < 8; nt++) {
                    int nn = half*8 + nt;
                    MMA(s[nn], aQ[0], bK[0][nt]);
                    MMA(s[nn], aQ[0], bK[1][nt]);
                    MMA(s[nn], aQ[1], bK[0][nt]);
                }
            }
        }

        // P = S^2, split to bf16 hi/lo in A-fragment layout
        uint32_t aP[2][8][4];
        #pragma unroll
        for (int kt2 = 0; kt2 < 8; kt2++) {
            float x0, x1;
            x0 = s[2*kt2][0]*s[2*kt2][0];     x1 = s[2*kt2][1]*s[2*kt2][1];
            split2(x0, x1, aP[0][kt2][0], aP[1][kt2][0]);
            x0 = s[2*kt2][2]*s[2*kt2][2];     x1 = s[2*kt2][3]*s[2*kt2][3];
            split2(x0, x1, aP[0][kt2][1], aP[1][kt2][1]);
            x0 = s[2*kt2+1][0]*s[2*kt2+1][0]; x1 = s[2*kt2+1][1]*s[2*kt2+1][1];
            split2(x0, x1, aP[0][kt2][2], aP[1][kt2][2]);
            x0 = s[2*kt2+1][2]*s[2*kt2+1][2]; x1 = s[2*kt2+1][3]*s[2*kt2+1][3];
            split2(x0, x1, aP[0][kt2][3], aP[1][kt2][3]);
        }

        // O += P V
        #pragma unroll
        for (int kt2 = 0; kt2 < 8; kt2++) {
            uint32_t bV[2][8][2];
            #pragma unroll
            for (int part = 0; part < 2; part++)
                #pragma unroll
                for (int nt2 = 0; nt2 < 4; nt2++) {
                    uint32_t r[4];
                    LDM4(r, uV[part] +
                         ((nt2*16 + bRowOff) * LDV + kt2*16 + bCol) * 2);
                    bV[part][nt2*2  ][0] = r[0]; bV[part][nt2*2  ][1] = r[1];
                    bV[part][nt2*2+1][0] = r[2]; bV[part][nt2*2+1][1] = r[3];
                }
            #pragma unroll
            for (int nt = 0; nt < 8; nt++) {
                MMA(o[nt], aP[0][kt2], bV[0][nt]);
                MMA(o[nt], aP[0][kt2], bV[1][nt]);
                MMA(o[nt], aP[1][kt2], bV[0][nt]);
            }
        }
        __syncthreads();
    }

    // ctx epilogue: split bf16, [b, s, DM]
    const int g = lane >> 2, tig = lane & 3;
    const int r0 = q0 + w*16 + g;
    const int b_ = bh >> 4, h_ = bh & 15;
    #pragma unroll
    for (int rr = 0; rr < 2; rr++) {
        const int s_ = r0 + rr*8;
        const size_t ob = ((size_t)b_ * SEQ + s_) * DM + h_ * DK;
        #pragma unroll
        for (int nt = 0; nt < 8; nt++) {
            uint32_t hp, lp;
            split2(o[nt][rr*2], o[nt][rr*2+1], hp, lp);
            *(uint32_t*)(ch + ob + nt*8 + tig*2) = hp;
            *(uint32_t*)(cl + ob + nt*8 + tig*2) = lp;
        }
    }
}

// ---------------------------------------------------------------------------
extern "C" void kernel_launch(void* const* d_in, const int* in_sizes, int n_in,
                              void* d_out, int out_size)
{
    const float* Q    = (const float*)d_in[0];
    const float* K    = (const float*)d_in[1];
    const float* V    = (const float*)d_in[2];
    const float* Wq_w = (const float*)d_in[3];
    const float* Wq_b = (const float*)d_in[4];
    const float* Wk_w = (const float*)d_in[5];
    const float* Wk_b = (const float*)d_in[6];
    const float* Wv_w = (const float*)d_in[7];
    const float* Wv_b = (const float*)d_in[8];
    const float* Wo_w = (const float*)d_in[9];
    const float* Wo_b = (const float*)d_in[10];
    float* out = (float*)d_out;

    __nv_bfloat16* gb;
    cudaGetSymbolAddress((void**)&gb, g_buf);

    __nv_bfloat16* xh[3] = { gb + OFF_XQH, gb + OFF_XKH, gb + OFF_XVH };
    __nv_bfloat16* xl[3] = { gb + OFF_XQL, gb + OFF_XKL, gb + OFF_XVL };
    __nv_bfloat16* wh[4]; __nv_bfloat16* wl[4];
    for (int i = 0; i < 4; i++) { wh[i] = gb + OFF_W + (size_t)(2*i) * NW; wl[i] = wh[i] + NW; }
    __nv_bfloat16 *qh = gb + OFF_QH, *ql = gb + OFF_QL;
    __nv_bfloat16 *kh = gb + OFF_KH, *kl = gb + OFF_KL;
    __nv_bfloat16 *vh = gb + OFF_VH, *vl = gb + OFF_VL;
    __nv_bfloat16 *ch = gb + OFF_CH, *cl = gb + OFF_CL;

    cudaFuncSetAttribute(gemm_mma, cudaFuncAttributeMaxDynamicSharedMemorySize, GEMM_SMEM);
    cudaFuncSetAttribute(attn_mma, cudaFuncAttributeMaxDynamicSharedMemorySize, ATTN_SMEM);

    const float* xin[3] = { Q, K, V };
    for (int i = 0; i < 3; i++)
        split_kernel<<<NX/8/256, 256>>>((const float4*)xin[i], (uint4*)xh[i], (uint4*)xl[i], NX/8);
    const float* win[4] = { Wq_w, Wk_w, Wv_w, Wo_w };
    for (int i = 0; i < 4; i++)
        split_kernel<<<NW/8/256, 256>>>((const float4*)win[i], (uint4*)wh[i], (uint4*)wl[i], NW/8);

    dim3 ggrid(DM/128, MTOT/128);   // (8, 32)
    gemm_mma<<<ggrid, 256, GEMM_SMEM>>>(xh[0], xl[0], wh[0], wl[0], Wq_b, nullptr, qh, ql, 3);
    gemm_mma<<<ggrid, 256, GEMM_SMEM>>>(xh[1], xl[1], wh[1], wl[1], Wk_b, nullptr, kh, kl, 3);
    gemm_mma<<<ggrid, 256, GEMM_SMEM>>>(xh[2], xl[2], wh[2], wl[2], Wv_b, nullptr, vh, vl, 1);

    dim3 agrid(SEQ/128, NBH);       // (16, 32)
    attn_mma<<<agrid, 256, ATTN_SMEM>>>(qh, ql, kh, kl, vh, vl, ch, cl);

    gemm_mma<<<ggrid, 256, GEMM_SMEM>>>(ch, cl, wh[3], wl[3], Wo_b, out, nullptr, nullptr, 0);
}

// round 4
// speedup vs baseline: 3.3574x; 1.2550x over previous
#include <cuda_runtime.h>
#include <cuda_bf16.h>
#include <stdint.h>

#define DM 1024
#define NH 16
#define DK 64
#define SEQ 2048
#define MTOT 4096
#define NBH 32
#define NX (MTOT*DM)   /* 4194304 */
#define NW (DM*DM)     /* 1048576 */
#define LDP 72         /* attn smem row stride (bf16) for 64-wide rows */
#define LDPG 40        /* gemm smem row stride (bf16) for 32-wide k-chunks */

// scratch arena
__device__ __nv_bfloat16 g_buf[14ull*NX + 8ull*NW];

#define OFF_XQH 0ull
#define OFF_XQL (1ull*NX)
#define OFF_XKH (2ull*NX)
#define OFF_XKL (3ull*NX)
#define OFF_XVH (4ull*NX)
#define OFF_XVL (5ull*NX)
#define OFF_W   (6ull*NX)
#define OFF_QH  (OFF_W + 8ull*NW)
#define OFF_QL  (OFF_QH + 1ull*NX)
#define OFF_KH  (OFF_QH + 2ull*NX)
#define OFF_KL  (OFF_QH + 3ull*NX)
#define OFF_VH  (OFF_QH + 4ull*NX)   /* transposed [b,h,d,s] */
#define OFF_VL  (OFF_QH + 5ull*NX)
#define OFF_CH  (OFF_QH + 6ull*NX)
#define OFF_CL  (OFF_QH + 7ull*NX)

static __device__ __forceinline__ uint32_t smem_u32(const void* p) {
    uint32_t a;
    asm("{ .reg .u64 t; cvta.to.shared.u64 t, %1; cvt.u32.u64 %0, t; }" : "=r"(a) : "l"(p));
    return a;
}

#define MMA(C, A, B) asm volatile( \
    "mma.sync.aligned.m16n8k16.row.col.f32.bf16.bf16.f32 " \
    "{%0,%1,%2,%3}, {%4,%5,%6,%7}, {%8,%9}, {%0,%1,%2,%3};" \
    : "+f"((C)[0]), "+f"((C)[1]), "+f"((C)[2]), "+f"((C)[3]) \
    : "r"((A)[0]), "r"((A)[1]), "r"((A)[2]), "r"((A)[3]), \
      "r"((B)[0]), "r"((B)[1]))

#define LDM4(R, ADDR) asm volatile( \
    "ldmatrix.sync.aligned.m8n8.x4.shared.b16 {%0,%1,%2,%3}, [%4];" \
    : "=r"((R)[0]), "=r"((R)[1]), "=r"((R)[2]), "=r"((R)[3]) : "r"(ADDR))

#define CP16(d, s) asm volatile("cp.async.cg.shared.global [%0], [%1], 16;" :: "r"(d), "l"(s))
#define CPC()   asm volatile("cp.async.commit_group;")
#define CPW(n)  asm volatile("cp.async.wait_group %0;" :: "n"(n))

static __device__ __forceinline__ void split2(float x0, float x1,
                                              uint32_t& hp, uint32_t& lp) {
    __nv_bfloat16 h0 = __float2bfloat16(x0), h1 = __float2bfloat16(x1);
    __nv_bfloat16 l0 = __float2bfloat16(x0 - __bfloat162float(h0));
    __nv_bfloat16 l1 = __float2bfloat16(x1 - __bfloat162float(h1));
    hp = (uint32_t)__bfloat16_as_ushort(h0) | ((uint32_t)__bfloat16_as_ushort(h1) << 16);
    lp = (uint32_t)__bfloat16_as_ushort(l0) | ((uint32_t)__bfloat16_as_ushort(l1) << 16);
}

// ---------------------------------------------------------------------------
// Fused split: up to 4 tensors, selected by blockIdx.y
// ---------------------------------------------------------------------------
struct SplitArgs {
    const float4* s[4];
    uint4* h[4];
    uint4* l[4];
};
__global__ void split_multi(SplitArgs a, int nchunks)
{
    const int y = blockIdx.y;
    const float4* src = a.s[y];
    uint4* hi = a.h[y];
    uint4* lo = a.l[y];
    int i = blockIdx.x * blockDim.x + threadIdx.x;
    if (i >= nchunks) return;
    float4 p = src[i*2], q = src[i*2+1];
    float v[8] = {p.x, p.y, p.z, p.w, q.x, q.y, q.z, q.w};
    uint4 H, L;
    split2(v[0], v[1], H.x, L.x);
    split2(v[2], v[3], H.y, L.y);
    split2(v[4], v[5], H.z, L.z);
    split2(v[6], v[7], H.w, L.w);
    hi[i] = H;
    lo[i] = L;
}

// ---------------------------------------------------------------------------
// GEMM: Y = A @ W^T + bias. CTA 128x128, k-step 32, 2-stage cp.async pipeline.
// 8 warps (warp tile 32x64), bf16 split-3 via mma.sync m16n8k16.
// mode 0: fp32 [M,DM]   mode 1: [b,h,d,s] split (V)   mode 3: [b,h,s,d] split + rownorm
// ---------------------------------------------------------------------------
#define G_ARR   (128*LDPG*2)        /* 10240 bytes per array */
#define G_STAGE (4*G_ARR)           /* 40960 */
#define GEMM_SMEM (2*G_STAGE)       /* 81920 */
__global__ void __launch_bounds__(256, 2) gemm_mma(
    const __nv_bfloat16* __restrict__ Ah, const __nv_bfloat16* __restrict__ Al,
    const __nv_bfloat16* __restrict__ Wh, const __nv_bfloat16* __restrict__ Wl,
    const float* __restrict__ bias, float* __restrict__ Yf,
    __nv_bfloat16* __restrict__ Yh, __nv_bfloat16* __restrict__ Yl, int mode)
{
    extern __shared__ char sm[];
    const uint32_t sb = smem_u32(sm);
    const int t = threadIdx.x, lane = t & 31, w = t >> 5;
    const int wm = w & 3, wn = w >> 2;
    const int n0 = blockIdx.x * 128, m0 = blockIdx.y * 128;

    const __nv_bfloat16* srcs[4] = {
        Ah + (size_t)m0 * DM, Al + (size_t)m0 * DM,
        Wh + (size_t)n0 * DM, Wl + (size_t)n0 * DM };

    const int lrow = t >> 2, lq = t & 3;           // chunk 0 mapping
    const int lrow2 = (t + 256) >> 2, lq2 = (t + 256) & 3;

#define G_LOAD(kt, st) do { \
    _Pragma("unroll") \
    for (int a_ = 0; a_ < 4; a_++) { \
        uint32_t dst0 = sb + (st)*G_STAGE + a_*G_ARR + (lrow*LDPG + lq*8)*2; \
        CP16(dst0, srcs[a_] + (size_t)lrow * DM + (kt) + lq*8); \
        uint32_t dst1 = sb + (st)*G_STAGE + a_*G_ARR + (lrow2*LDPG + lq2*8)*2; \
        CP16(dst1, srcs[a_] + (size_t)lrow2 * DM + (kt) + lq2*8); \
    } \
    CPC(); \
} while (0)

    float acc[2][8][4];
    #pragma unroll
    for (int i = 0; i < 2; i++)
        #pragma unroll
        for (int j = 0; j < 8; j++)
            #pragma unroll
            for (int k = 0; k < 4; k++) acc[i][j][k] = 0.f;

    const int aRow = wm*32 + (lane & 15);
    const int aCol = (lane >> 4) * 8;
    const int bRowOff = wn*64 + (lane & 7) + ((lane >> 4) << 3);
    const int bCol = ((lane >> 3) & 1) * 8;

    G_LOAD(0, 0);
    G_LOAD(32, 1);
    CPW(1);
    __syncthreads();

    int st = 0;
    #pragma unroll 1
    for (int kc = 0; kc < 32; kc++) {
        const uint32_t uAh = sb + st*G_STAGE;
        const uint32_t uAl = uAh + G_ARR;
        const uint32_t uBh = uAh + 2*G_ARR;
        const uint32_t uBl = uAh + 3*G_ARR;
        #pragma unroll
        for (int ks = 0; ks < 2; ks++) {
            uint32_t aF[2][2][4];
            #pragma unroll
            for (int mt = 0; mt < 2; mt++) {
                LDM4(aF[0][mt], uAh + ((aRow + mt*16)*LDPG + ks*16 + aCol)*2);
                LDM4(aF[1][mt], uAl + ((aRow + mt*16)*LDPG + ks*16 + aCol)*2);
            }
            #pragma unroll
            for (int nt2 = 0; nt2 < 4; nt2++) {
                uint32_t rh[4], rl[4];
                LDM4(rh, uBh + ((nt2*16 + bRowOff)*LDPG + ks*16 + bCol)*2);
                LDM4(rl, uBl + ((nt2*16 + bRowOff)*LDPG + ks*16 + bCol)*2);
                uint32_t bh0[2] = {rh[0], rh[1]}, bh1[2] = {rh[2], rh[3]};
                uint32_t bl0[2] = {rl[0], rl[1]}, bl1[2] = {rl[2], rl[3]};
                #pragma unroll
                for (int mt = 0; mt < 2; mt++) {
                    MMA(acc[mt][nt2*2  ], aF[0][mt], bh0);
                    MMA(acc[mt][nt2*2  ], aF[0][mt], bl0);
                    MMA(acc[mt][nt2*2  ], aF[1][mt], bh0);
                    MMA(acc[mt][nt2*2+1], aF[0][mt], bh1);
                    MMA(acc[mt][nt2*2+1], aF[0][mt], bl1);
                    MMA(acc[mt][nt2*2+1], aF[1][mt], bh1);
                }
            }
        }
        __syncthreads();
        if (kc + 2 < 32) {
            G_LOAD((kc + 2) * 32, st);
            CPW(1);
            __syncthreads();
        } else if (kc + 1 < 32) {
            CPW(0);
            __syncthreads();
        }
        st ^= 1;
    }

    // ---- epilogue ----
    const int g = lane >> 2, tig = lane & 3;
    #pragma unroll
    for (int mt = 0; mt < 2; mt++) {
        const int r0 = m0 + wm*32 + mt*16 + g;
        float v[2][8][2];
        #pragma unroll
        for (int nt = 0; nt < 8; nt++) {
            int col = n0 + wn*64 + nt*8 + tig*2;
            float b0v = bias[col], b1v = bias[col + 1];
            v[0][nt][0] = acc[mt][nt][0] + b0v;
            v[0][nt][1] = acc[mt][nt][1] + b1v;
            v[1][nt][0] = acc[mt][nt][2] + b0v;
            v[1][nt][1] = acc[mt][nt][3] + b1v;
        }
        if (mode == 0) {
            #pragma unroll
            for (int rr = 0; rr < 2; rr++) {
                int r = r0 + rr*8;
                #pragma unroll
                for (int nt = 0; nt < 8; nt++) {
                    int col = n0 + wn*64 + nt*8 + tig*2;
                    *(float2*)(Yf + (size_t)r * DM + col) =
                        make_float2(v[rr][nt][0], v[rr][nt][1]);
                }
            }
        } else {
            if (mode == 3) {
                #pragma unroll
                for (int rr = 0; rr < 2; rr++) {
                    float ss = 0.f;
                    #pragma unroll
                    for (int nt = 0; nt < 8; nt++)
                        ss += v[rr][nt][0]*v[rr][nt][0] + v[rr][nt][1]*v[rr][nt][1];
                    ss += __shfl_xor_sync(0xffffffffu, ss, 1);
                    ss += __shfl_xor_sync(0xffffffffu, ss, 2);
                    float inv = rsqrtf(ss + 1e-8f);
                    #pragma unroll
                    for (int nt = 0; nt < 8; nt++) {
                        v[rr][nt][0] *= inv;
                        v[rr][nt][1] *= inv;
                    }
                }
            }
            const int h_ = (n0 >> 6) + wn;
            const int b_ = r0 >> 11;
            #pragma unroll
            for (int rr = 0; rr < 2; rr++) {
                const int s_ = (r0 + rr*8) & 2047;
                if (mode == 1) {
                    const size_t base = (size_t)(b_ * NH + h_) * DK;
                    #pragma unroll
                    for (int nt = 0; nt < 8; nt++) {
                        int d = nt*8 + tig*2;
                        float x0 = v[rr][nt][0], x1 = v[rr][nt][1];
                        __nv_bfloat16 h0 = __float2bfloat16(x0);
                        __nv_bfloat16 h1 = __float2bfloat16(x1);
                        Yh[(base + d    ) * SEQ + s_] = h0;
                        Yh[(base + d + 1) * SEQ + s_] = h1;
                        Yl[(base + d    ) * SEQ + s_] =
                            __float2bfloat16(x0 - __bfloat162float(h0));
                        Yl[(base + d + 1) * SEQ + s_] =
                            __float2bfloat16(x1 - __bfloat162float(h1));
                    }
                } else {
                    const size_t base = ((size_t)(b_ * NH + h_) * SEQ + s_) * DK;
                    #pragma unroll
                    for (int nt = 0; nt < 8; nt++) {
                        uint32_t hp, lp;
                        split2(v[rr][nt][0], v[rr][nt][1], hp, lp);
                        *(uint32_t*)(Yh + base + nt*8 + tig*2) = hp;
                        *(uint32_t*)(Yl + base + nt*8 + tig*2) = lp;
                    }
                }
            }
        }
    }
#undef G_LOAD
}

// ---------------------------------------------------------------------------
// Attention: CTA = (bh, 128-q tile), 64-key tiles, 2-stage cp.async pipeline.
//   S = Qn Kn^T (split-3) -> square+split in regs -> O += P V (split-3)
// ---------------------------------------------------------------------------
#define A_QARR (128*LDP*2)            /* 18432 */
#define A_KARR (64*LDP*2)             /* 9216  */
#define A_STAGE (4*A_KARR)            /* 36864: Kh Kl Vh Vl */
#define A_STAGE0 (2*A_QARR)           /* 36864 */
#define ATTN_SMEM (A_STAGE0 + 2*A_STAGE)   /* 110592 */
__global__ void __launch_bounds__(256, 2) attn_mma(
    const __nv_bfloat16* __restrict__ qhp, const __nv_bfloat16* __restrict__ qlp,
    const __nv_bfloat16* __restrict__ khp, const __nv_bfloat16* __restrict__ klp,
    const __nv_bfloat16* __restrict__ vhp, const __nv_bfloat16* __restrict__ vlp,
    __nv_bfloat16* __restrict__ ch, __nv_bfloat16* __restrict__ cl)
{
    extern __shared__ char sm[];
    const uint32_t sb = smem_u32(sm);
    const int t = threadIdx.x, lane = t & 31, w = t >> 5;
    const int q0 = blockIdx.x * 128;
    const int bh = blockIdx.y;
    const size_t base = (size_t)bh * SEQ * DK;

    const __nv_bfloat16* Ksrc[2] = { khp + base, klp + base };
    const __nv_bfloat16* Vsrc[2] = { vhp + base, vlp + base };

    const int krow = t >> 3, kq = t & 7;               // 0..31 rows x 8 chunks? (row=t>>3: 0..31)
    const int krow2 = (t + 256) >> 3, kq2 = (t + 256) & 7;

#define A_LOADKV(kt, st) do { \
    _Pragma("unroll") \
    for (int p_ = 0; p_ < 2; p_++) { \
        uint32_t dK0 = sb + A_STAGE0 + (st)*A_STAGE + p_*A_KARR + (krow*LDP + kq*8)*2; \
        CP16(dK0, Ksrc[p_] + (size_t)((kt) + krow) * DK + kq*8); \
        uint32_t dK1 = sb + A_STAGE0 + (st)*A_STAGE + p_*A_KARR + (krow2*LDP + kq2*8)*2; \
        CP16(dK1, Ksrc[p_] + (size_t)((kt) + krow2) * DK + kq2*8); \
        uint32_t dV0 = sb + A_STAGE0 + (st)*A_STAGE + (2+p_)*A_KARR + (krow*LDP + kq*8)*2; \
        CP16(dV0, Vsrc[p_] + (size_t)krow * SEQ + (kt) + kq*8); \
        uint32_t dV1 = sb + A_STAGE0 + (st)*A_STAGE + (2+p_)*A_KARR + (krow2*LDP + kq2*8)*2; \
        CP16(dV1, Vsrc[p_] + (size_t)krow2 * SEQ + (kt) + kq2*8); \
    } \
    CPC(); \
} while (0)

    // Q loads (part of commit group 0)
    {
        const __nv_bfloat16* Qsrc[2] = { qhp + base, qlp + base };
        #pragma unroll
        for (int p_ = 0; p_ < 2; p_++)
            #pragma unroll
            for (int i = 0; i < 4; i++) {
                int c = t + i*256, row = c >> 3, q = c & 7;
                uint32_t dst = sb + p_*A_QARR + (row*LDP + q*8)*2;
                CP16(dst, Qsrc[p_] + (size_t)(q0 + row) * DK + q*8);
            }
    }
    A_LOADKV(0, 0);
    A_LOADKV(64, 1);
    CPW(1);
    __syncthreads();

    const int aRow = w*16 + (lane & 15);
    const int aCol = (lane >> 4) * 8;
    const int bRowOff = (lane & 7) + ((lane >> 4) << 3);
    const int bCol = ((lane >> 3) & 1) * 8;

    float o[8][4];
    #pragma unroll
    for (int i = 0; i < 8; i++)
        #pragma unroll
        for (int j = 0; j < 4; j++) o[i][j] = 0.f;

    int st = 0;
    #pragma unroll 1
    for (int kc = 0; kc < 32; kc++) {
        const uint32_t uKh = sb + A_STAGE0 + st*A_STAGE;
        const uint32_t uKl = uKh + A_KARR;
        const uint32_t uVh = uKh + 2*A_KARR;
        const uint32_t uVl = uKh + 3*A_KARR;

        // S = Qn Kn^T over 64 keys
        float s[8][4];
        #pragma unroll
        for (int i = 0; i < 8; i++)
            #pragma unroll
            for (int j = 0; j < 4; j++) s[i][j] = 0.f;

        #pragma unroll
        for (int ks = 0; ks < 4; ks++) {
            uint32_t aQh[4], aQl[4];
            LDM4(aQh, sb + (aRow*LDP + ks*16 + aCol)*2);
            LDM4(aQl, sb + A_QARR + (aRow*LDP + ks*16 + aCol)*2);
            #pragma unroll
            for (int nt2 = 0; nt2 < 4; nt2++) {
                uint32_t rh[4], rl[4];
                LDM4(rh, uKh + ((nt2*16 + bRowOff)*LDP + ks*16 + bCol)*2);
                LDM4(rl, uKl + ((nt2*16 + bRowOff)*LDP + ks*16 + bCol)*2);
                uint32_t bh0[2] = {rh[0], rh[1]}, bh1[2] = {rh[2], rh[3]};
                uint32_t bl0[2] = {rl[0], rl[1]}, bl1[2] = {rl[2], rl[3]};
                MMA(s[nt2*2  ], aQh, bh0);
                MMA(s[nt2*2  ], aQh, bl0);
                MMA(s[nt2*2  ], aQl, bh0);
                MMA(s[nt2*2+1], aQh, bh1);
                MMA(s[nt2*2+1], aQh, bl1);
                MMA(s[nt2*2+1], aQl, bh1);
            }
        }

        // P = S^2 split-3, O += P V (per 16-key chunk to keep registers low)
        #pragma unroll
        for (int kt2 = 0; kt2 < 4; kt2++) {
            uint32_t aPh[4], aPl[4];
            {
                float x0, x1;
                x0 = s[2*kt2][0]*s[2*kt2][0];     x1 = s[2*kt2][1]*s[2*kt2][1];
                split2(x0, x1, aPh[0], aPl[0]);
                x0 = s[2*kt2][2]*s[2*kt2][2];     x1 = s[2*kt2][3]*s[2*kt2][3];
                split2(x0, x1, aPh[1], aPl[1]);
                x0 = s[2*kt2+1][0]*s[2*kt2+1][0]; x1 = s[2*kt2+1][1]*s[2*kt2+1][1];
                split2(x0, x1, aPh[2], aPl[2]);
                x0 = s[2*kt2+1][2]*s[2*kt2+1][2]; x1 = s[2*kt2+1][3]*s[2*kt2+1][3];
                split2(x0, x1, aPh[3], aPl[3]);
            }
            #pragma unroll
            for (int nt2 = 0; nt2 < 4; nt2++) {
                uint32_t rh[4], rl[4];
                LDM4(rh, uVh + ((nt2*16 + bRowOff)*LDP + kt2*16 + bCol)*2);
                LDM4(rl, uVl + ((nt2*16 + bRowOff)*LDP + kt2*16 + bCol)*2);
                uint32_t bh0[2] = {rh[0], rh[1]}, bh1[2] = {rh[2], rh[3]};
                uint32_t bl0[2] = {rl[0], rl[1]}, bl1[2] = {rl[2], rl[3]};
                MMA(o[nt2*2  ], aPh, bh0);
                MMA(o[nt2*2  ], aPh, bl0);
                MMA(o[nt2*2  ], aPl, bh0);
                MMA(o[nt2*2+1], aPh, bh1);
                MMA(o[nt2*2+1], aPh, bl1);
                MMA(o[nt2*2+1], aPl, bh1);
            }
        }

        __syncthreads();
        if (kc + 2 < 32) {
            A_LOADKV((kc + 2) * 64, st);
            CPW(1);
            __syncthreads();
        } else if (kc + 1 < 32) {
            CPW(0);
            __syncthreads();
        }
        st ^= 1;
    }

    // ctx epilogue: split bf16, [b, s, DM]
    const int g = lane >> 2, tig = lane & 3;
    const int r0 = q0 + w*16 + g;
    const int b_ = bh >> 4, h_ = bh & 15;
    #pragma unroll
    for (int rr = 0; rr < 2; rr++) {
        const int s_ = r0 + rr*8;
        const size_t ob = ((size_t)b_ * SEQ + s_) * DM + h_ * DK;
        #pragma unroll
        for (int nt = 0; nt < 8; nt++) {
            uint32_t hp, lp;
            split2(o[nt][rr*2], o[nt][rr*2+1], hp, lp);
            *(uint32_t*)(ch + ob + nt*8 + tig*2) = hp;
            *(uint32_t*)(cl + ob + nt*8 + tig*2) = lp;
        }
    }
#undef A_LOADKV
}

// ---------------------------------------------------------------------------
extern "C" void kernel_launch(void* const* d_in, const int* in_sizes, int n_in,
                              void* d_out, int out_size)
{
    const float* Q    = (const float*)d_in[0];
    const float* K    = (const float*)d_in[1];
    const float* V    = (const float*)d_in[2];
    const float* Wq_w = (const float*)d_in[3];
    const float* Wq_b = (const float*)d_in[4];
    const float* Wk_w = (const float*)d_in[5];
    const float* Wk_b = (const float*)d_in[6];
    const float* Wv_w = (const float*)d_in[7];
    const float* Wv_b = (const float*)d_in[8];
    const float* Wo_w = (const float*)d_in[9];
    const float* Wo_b = (const float*)d_in[10];
    float* out = (float*)d_out;

    __nv_bfloat16* gb;
    cudaGetSymbolAddress((void**)&gb, g_buf);

    __nv_bfloat16* xh[3] = { gb + OFF_XQH, gb + OFF_XKH, gb + OFF_XVH };
    __nv_bfloat16* xl[3] = { gb + OFF_XQL, gb + OFF_XKL, gb + OFF_XVL };
    __nv_bfloat16* wh[4]; __nv_bfloat16* wl[4];
    for (int i = 0; i < 4; i++) { wh[i] = gb + OFF_W + (size_t)(2*i) * NW; wl[i] = wh[i] + NW; }
    __nv_bfloat16 *qh = gb + OFF_QH, *ql = gb + OFF_QL;
    __nv_bfloat16 *kh = gb + OFF_KH, *kl = gb + OFF_KL;
    __nv_bfloat16 *vh = gb + OFF_VH, *vl = gb + OFF_VL;
    __nv_bfloat16 *ch = gb + OFF_CH, *cl = gb + OFF_CL;

    cudaFuncSetAttribute(gemm_mma, cudaFuncAttributeMaxDynamicSharedMemorySize, GEMM_SMEM);
    cudaFuncSetAttribute(attn_mma, cudaFuncAttributeMaxDynamicSharedMemorySize, ATTN_SMEM);

    // fused splits: inputs (3 tensors), weights (4 tensors)
    SplitArgs ia;
    ia.s[0] = (const float4*)Q; ia.s[1] = (const float4*)K; ia.s[2] = (const float4*)V;
    ia.s[3] = (const float4*)Q;
    for (int i = 0; i < 3; i++) { ia.h[i] = (uint4*)xh[i]; ia.l[i] = (uint4*)xl[i]; }
    ia.h[3] = (uint4*)xh[0]; ia.l[3] = (uint4*)xl[0];
    split_multi<<<dim3(NX/8/256, 3), 256>>>(ia, NX/8);

    SplitArgs wa;
    wa.s[0] = (const float4*)Wq_w; wa.s[1] = (const float4*)Wk_w;
    wa.s[2] = (const float4*)Wv_w; wa.s[3] = (const float4*)Wo_w;
    for (int i = 0; i < 4; i++) { wa.h[i] = (uint4*)wh[i]; wa.l[i] = (uint4*)wl[i]; }
    split_multi<<<dim3(NW/8/256, 4), 256>>>(wa, NW/8);

    dim3 ggrid(DM/128, MTOT/128);   // (8, 32)
    gemm_mma<<<ggrid, 256, GEMM_SMEM>>>(xh[0], xl[0], wh[0], wl[0], Wq_b, nullptr, qh, ql, 3);
    gemm_mma<<<ggrid, 256, GEMM_SMEM>>>(xh[1], xl[1], wh[1], wl[1], Wk_b, nullptr, kh, kl, 3);
    gemm_mma<<<ggrid, 256, GEMM_SMEM>>>(xh[2], xl[2], wh[2], wl[2], Wv_b, nullptr, vh, vl, 1);

    dim3 agrid(SEQ/128, NBH);       // (16, 32)
    attn_mma<<<agrid, 256, ATTN_SMEM>>>(qh, ql, kh, kl, vh, vl, ch, cl);

    gemm_mma<<<ggrid, 256, GEMM_SMEM>>>(ch, cl, wh[3], wl[3], Wo_b, out, nullptr, nullptr, 0);
}

// round 6
// speedup vs baseline: 3.7354x; 1.1126x over previous
#include <cuda_runtime.h>
#include <cuda_bf16.h>
#include <stdint.h>

#define DM 1024
#define NH 16
#define DK 64
#define SEQ 2048
#define MTOT 4096
#define NBH 32
#define NX (MTOT*DM)
#define NW (DM*DM)

// scratch arena
__device__ __nv_bfloat16 g_buf[14ull*NX + 8ull*NW];

#define OFF_XQH 0ull
#define OFF_XQL (1ull*NX)
#define OFF_XKH (2ull*NX)
#define OFF_XKL (3ull*NX)
#define OFF_XVH (4ull*NX)
#define OFF_XVL (5ull*NX)
#define OFF_W   (6ull*NX)
#define OFF_QH  (OFF_W + 8ull*NW)
#define OFF_QL  (OFF_QH + 1ull*NX)
#define OFF_KH  (OFF_QH + 2ull*NX)
#define OFF_KL  (OFF_QH + 3ull*NX)
#define OFF_VH  (OFF_QH + 4ull*NX)   /* transposed [b,h,d,s] */
#define OFF_VL  (OFF_QH + 5ull*NX)
#define OFF_CH  (OFF_QH + 6ull*NX)
#define OFF_CL  (OFF_QH + 7ull*NX)

static __device__ __forceinline__ uint32_t smem_u32(const void* p) {
    uint32_t a;
    asm("{ .reg .u64 t; cvta.to.shared.u64 t, %1; cvt.u32.u64 %0, t; }" : "=r"(a) : "l"(p));
    return a;
}

#define MMA(C, A, B) asm volatile( \
    "mma.sync.aligned.m16n8k16.row.col.f32.bf16.bf16.f32 " \
    "{%0,%1,%2,%3}, {%4,%5,%6,%7}, {%8,%9}, {%0,%1,%2,%3};" \
    : "+f"((C)[0]), "+f"((C)[1]), "+f"((C)[2]), "+f"((C)[3]) \
    : "r"((A)[0]), "r"((A)[1]), "r"((A)[2]), "r"((A)[3]), \
      "r"((B)[0]), "r"((B)[1]))

#define LDM4(R, ADDR) asm volatile( \
    "ldmatrix.sync.aligned.m8n8.x4.shared.b16 {%0,%1,%2,%3}, [%4];" \
    : "=r"((R)[0]), "=r"((R)[1]), "=r"((R)[2]), "=r"((R)[3]) : "r"(ADDR))

#define CP16(d, s) asm volatile("cp.async.cg.shared.global [%0], [%1], 16;" :: "r"(d), "l"(s))
#define CPC()   asm volatile("cp.async.commit_group;")
#define CPW(n)  asm volatile("cp.async.wait_group %0;" :: "n"(n))

// swizzles (byte offsets). SWC: 64B rows (4x16B chunks). SWK: 128B rows (8x16B chunks).
#define SWC(row, ch) (((row) << 6) + ((((ch) ^ (((row) >> 1) & 3))) << 4))
#define SWK(row, ch) (((row) << 7) + ((((ch) ^ ((row) & 7))) << 4))

static __device__ __forceinline__ void split2(float x0, float x1,
                                              uint32_t& hp, uint32_t& lp) {
    __nv_bfloat16 h0 = __float2bfloat16(x0), h1 = __float2bfloat16(x1);
    __nv_bfloat16 l0 = __float2bfloat16(x0 - __bfloat162float(h0));
    __nv_bfloat16 l1 = __float2bfloat16(x1 - __bfloat162float(h1));
    hp = (uint32_t)__bfloat16_as_ushort(h0) | ((uint32_t)__bfloat16_as_ushort(h1) << 16);
    lp = (uint32_t)__bfloat16_as_ushort(l0) | ((uint32_t)__bfloat16_as_ushort(l1) << 16);
}

// ---------------------------------------------------------------------------
struct SplitArgs {
    const float4* s[4];
    uint4* h[4];
    uint4* l[4];
};
__global__ void split_multi(SplitArgs a, int nchunks)
{
    const int y = blockIdx.y;
    const float4* src = a.s[y];
    uint4* hi = a.h[y];
    uint4* lo = a.l[y];
    int i = blockIdx.x * blockDim.x + threadIdx.x;
    if (i >= nchunks) return;
    float4 p = src[i*2], q = src[i*2+1];
    float v[8] = {p.x, p.y, p.z, p.w, q.x, q.y, q.z, q.w};
    uint4 H, L;
    split2(v[0], v[1], H.x, L.x);
    split2(v[2], v[3], H.y, L.y);
    split2(v[4], v[5], H.z, L.z);
    split2(v[6], v[7], H.w, L.w);
    hi[i] = H;
    lo[i] = L;
}

// ---------------------------------------------------------------------------
// GEMM: Y = A @ W^T + bias. CTA 128x128, k-step 32, 3-stage cp.async pipeline,
// single __syncthreads per k-step. Swizzled smem (no pad).
// ---------------------------------------------------------------------------
#define G_ARR   8192                 /* 128 rows x 64B */
#define G_STAGE (4*G_ARR)            /* 32768: Ah Al Wh Wl */
#define GEMM_SMEM (3*G_STAGE)        /* 98304 */
__global__ void __launch_bounds__(256, 2) gemm_mma(
    const __nv_bfloat16* __restrict__ Ah, const __nv_bfloat16* __restrict__ Al,
    const __nv_bfloat16* __restrict__ Wh, const __nv_bfloat16* __restrict__ Wl,
    const float* __restrict__ bias, float* __restrict__ Yf,
    __nv_bfloat16* __restrict__ Yh, __nv_bfloat16* __restrict__ Yl, int mode)
{
    extern __shared__ char sm[];
    const uint32_t sb = smem_u32(sm);
    const int t = threadIdx.x, lane = t & 31, w = t >> 5;
    const int wm = w & 3, wn = w >> 2;
    const int n0 = blockIdx.x * 128, m0 = blockIdx.y * 128;

    const __nv_bfloat16* srcs[4] = {
        Ah + (size_t)m0 * DM, Al + (size_t)m0 * DM,
        Wh + (size_t)n0 * DM, Wl + (size_t)n0 * DM };

    const int lrow = t >> 2, lch = t & 3;   // rows 0..63; +64 for second chunk

#define G_LOAD(kt, st) do { \
    _Pragma("unroll") \
    for (int a_ = 0; a_ < 4; a_++) { \
        uint32_t d0 = sb + (st)*G_STAGE + a_*G_ARR + SWC(lrow, lch); \
        CP16(d0, srcs[a_] + (size_t)lrow * DM + (kt) + lch*8); \
        uint32_t d1 = sb + (st)*G_STAGE + a_*G_ARR + SWC(lrow + 64, lch); \
        CP16(d1, srcs[a_] + (size_t)(lrow + 64) * DM + (kt) + lch*8); \
    } \
} while (0)

    float acc[2][8][4];
    #pragma unroll
    for (int i = 0; i < 2; i++)
        #pragma unroll
        for (int j = 0; j < 8; j++)
            #pragma unroll
            for (int k = 0; k < 4; k++) acc[i][j][k] = 0.f;

    const int aRow0 = wm*32 + (lane & 15);
    const int aChH  = lane >> 4;                 // 0/1 k-half chunk
    const int bRowOff = wn*64 + (lane & 7) + ((lane >> 4) << 3);
    const int bChH  = (lane >> 3) & 1;

    G_LOAD(0, 0);  CPC();
    G_LOAD(32, 1); CPC();

    int st = 0;
    #pragma unroll 1
    for (int kc = 0; kc < 32; kc++) {
        CPW(1);
        __syncthreads();
        // prefetch stage kc+2 into the buffer computed last iteration
        if (kc + 2 < 32) {
            int wr = st - 1 < 0 ? 2 : st - 1;
            G_LOAD((kc + 2) * 32, wr);
        }
        CPC();

        const uint32_t uAh = sb + st*G_STAGE;
        const uint32_t uAl = uAh + G_ARR;
        const uint32_t uBh = uAh + 2*G_ARR;
        const uint32_t uBl = uAh + 3*G_ARR;

        #pragma unroll
        for (int ks = 0; ks < 2; ks++) {
            uint32_t aF[2][2][4];
            #pragma unroll
            for (int mt = 0; mt < 2; mt++) {
                int r = aRow0 + mt*16;
                int c = ks*2 + aChH;
                LDM4(aF[0][mt], uAh + SWC(r, c));
                LDM4(aF[1][mt], uAl + SWC(r, c));
            }
            #pragma unroll
            for (int nt2 = 0; nt2 < 4; nt2++) {
                int r = bRowOff + nt2*16;
                int c = ks*2 + bChH;
                uint32_t rh[4], rl[4];
                LDM4(rh, uBh + SWC(r, c));
                LDM4(rl, uBl + SWC(r, c));
                uint32_t bh0[2] = {rh[0], rh[1]}, bh1[2] = {rh[2], rh[3]};
                uint32_t bl0[2] = {rl[0], rl[1]}, bl1[2] = {rl[2], rl[3]};
                const int nA = nt2*2, nB = nt2*2 + 1;
                // term-outer ordering: hh, hl, lh (chain distance 4)
                MMA(acc[0][nA], aF[0][0], bh0); MMA(acc[0][nB], aF[0][0], bh1);
                MMA(acc[1][nA], aF[0][1], bh0); MMA(acc[1][nB], aF[0][1], bh1);
                MMA(acc[0][nA], aF[0][0], bl0); MMA(acc[0][nB], aF[0][0], bl1);
                MMA(acc[1][nA], aF[0][1], bl0); MMA(acc[1][nB], aF[0][1], bl1);
                MMA(acc[0][nA], aF[1][0], bh0); MMA(acc[0][nB], aF[1][0], bh1);
                MMA(acc[1][nA], aF[1][1], bh0); MMA(acc[1][nB], aF[1][1], bh1);
            }
        }
        st = st + 1 == 3 ? 0 : st + 1;
    }

    // ---- epilogue ----
    const int g = lane >> 2, tig = lane & 3;
    #pragma unroll
    for (int mt = 0; mt < 2; mt++) {
        const int r0 = m0 + wm*32 + mt*16 + g;
        float v[2][8][2];
        #pragma unroll
        for (int nt = 0; nt < 8; nt++) {
            int col = n0 + wn*64 + nt*8 + tig*2;
            float b0v = bias[col], b1v = bias[col + 1];
            v[0][nt][0] = acc[mt][nt][0] + b0v;
            v[0][nt][1] = acc[mt][nt][1] + b1v;
            v[1][nt][0] = acc[mt][nt][2] + b0v;
            v[1][nt][1] = acc[mt][nt][3] + b1v;
        }
        if (mode == 0) {
            #pragma unroll
            for (int rr = 0; rr < 2; rr++) {
                int r = r0 + rr*8;
                #pragma unroll
                for (int nt = 0; nt < 8; nt++) {
                    int col = n0 + wn*64 + nt*8 + tig*2;
                    *(float2*)(Yf + (size_t)r * DM + col) =
                        make_float2(v[rr][nt][0], v[rr][nt][1]);
                }
            }
        } else {
            if (mode == 3) {
                #pragma unroll
                for (int rr = 0; rr < 2; rr++) {
                    float ss = 0.f;
                    #pragma unroll
                    for (int nt = 0; nt < 8; nt++)
                        ss += v[rr][nt][0]*v[rr][nt][0] + v[rr][nt][1]*v[rr][nt][1];
                    ss += __shfl_xor_sync(0xffffffffu, ss, 1);
                    ss += __shfl_xor_sync(0xffffffffu, ss, 2);
                    float inv = rsqrtf(ss + 1e-8f);
                    #pragma unroll
                    for (int nt = 0; nt < 8; nt++) {
                        v[rr][nt][0] *= inv;
                        v[rr][nt][1] *= inv;
                    }
                }
            }
            const int h_ = (n0 >> 6) + wn;
            const int b_ = r0 >> 11;
            #pragma unroll
            for (int rr = 0; rr < 2; rr++) {
                const int s_ = (r0 + rr*8) & 2047;
                if (mode == 1) {
                    const size_t base = (size_t)(b_ * NH + h_) * DK;
                    #pragma unroll
                    for (int nt = 0; nt < 8; nt++) {
                        int d = nt*8 + tig*2;
                        float x0 = v[rr][nt][0], x1 = v[rr][nt][1];
                        __nv_bfloat16 h0 = __float2bfloat16(x0);
                        __nv_bfloat16 h1 = __float2bfloat16(x1);
                        Yh[(base + d    ) * SEQ + s_] = h0;
                        Yh[(base + d + 1) * SEQ + s_] = h1;
                        Yl[(base + d    ) * SEQ + s_] =
                            __float2bfloat16(x0 - __bfloat162float(h0));
                        Yl[(base + d + 1) * SEQ + s_] =
                            __float2bfloat16(x1 - __bfloat162float(h1));
                    }
                } else {
                    const size_t base = ((size_t)(b_ * NH + h_) * SEQ + s_) * DK;
                    #pragma unroll
                    for (int nt = 0; nt < 8; nt++) {
                        uint32_t hp, lp;
                        split2(v[rr][nt][0], v[rr][nt][1], hp, lp);
                        *(uint32_t*)(Yh + base + nt*8 + tig*2) = hp;
                        *(uint32_t*)(Yl + base + nt*8 + tig*2) = lp;
                    }
                }
            }
        }
    }
#undef G_LOAD
}

// ---------------------------------------------------------------------------
// Attention: CTA = (bh, 128-q tile), 64-key chunks, 2-stage cp.async, swizzled.
// ---------------------------------------------------------------------------
#define A_QARR  16384                 /* 128 rows x 128B */
#define A_KARR  8192                  /* 64 rows x 128B */
#define A_STAGE (4*A_KARR)            /* 32768: Kh Kl Vh Vl */
#define A_QTOT  (2*A_QARR)            /* 32768 */
#define ATTN_SMEM (A_QTOT + 2*A_STAGE)   /* 98304 */
__global__ void __launch_bounds__(256, 2) attn_mma(
    const __nv_bfloat16* __restrict__ qhp, const __nv_bfloat16* __restrict__ qlp,
    const __nv_bfloat16* __restrict__ khp, const __nv_bfloat16* __restrict__ klp,
    const __nv_bfloat16* __restrict__ vhp, const __nv_bfloat16* __restrict__ vlp,
    __nv_bfloat16* __restrict__ ch, __nv_bfloat16* __restrict__ cl)
{
    extern __shared__ char sm[];
    const uint32_t sb = smem_u32(sm);
    const int t = threadIdx.x, lane = t & 31, w = t >> 5;
    const int q0 = blockIdx.x * 128;
    const int bh = blockIdx.y;
    const size_t base = (size_t)bh * SEQ * DK;

    const __nv_bfloat16* Ksrc[2] = { khp + base, klp + base };
    const __nv_bfloat16* Vsrc[2] = { vhp + base, vlp + base };

    const int krow = t >> 2, kch = t & 3;   // 64 rows; chunks kch and kch+4

#define A_LOADKV(kt, st) do { \
    _Pragma("unroll") \
    for (int p_ = 0; p_ < 2; p_++) { \
        uint32_t kb = sb + A_QTOT + (st)*A_STAGE + p_*A_KARR; \
        CP16(kb + SWK(krow, kch),     Ksrc[p_] + (size_t)((kt) + krow) * DK + kch*8); \
        CP16(kb + SWK(krow, kch + 4), Ksrc[p_] + (size_t)((kt) + krow) * DK + (kch + 4)*8); \
        uint32_t vb = sb + A_QTOT + (st)*A_STAGE + (2+p_)*A_KARR; \
        CP16(vb + SWK(krow, kch),     Vsrc[p_] + (size_t)krow * SEQ + (kt) + kch*8); \
        CP16(vb + SWK(krow, kch + 4), Vsrc[p_] + (size_t)krow * SEQ + (kt) + (kch + 4)*8); \
    } \
} while (0)

    // Q loads: 128 rows x 8 chunks per part (1024 CP16s per part)
    {
        const __nv_bfloat16* Qsrc[2] = { qhp + base, qlp + base };
        #pragma unroll
        for (int p_ = 0; p_ < 2; p_++)
            #pragma unroll
            for (int i = 0; i < 4; i++) {
                int c = t + i*256, row = c >> 3, chn = c & 7;
                CP16(sb + p_*A_QARR + SWK(row, chn),
                     Qsrc[p_] + (size_t)(q0 + row) * DK + chn*8);
            }
    }
    A_LOADKV(0, 0);  CPC();
    A_LOADKV(64, 1); CPC();
    CPW(1);
    __syncthreads();

    const int aRow = w*16 + (lane & 15);
    const int aChH = lane >> 4;
    const int bRowOff = (lane & 7) + ((lane >> 4) << 3);
    const int bChH = (lane >> 3) & 1;

    float o[8][4];
    #pragma unroll
    for (int i = 0; i < 8; i++)
        #pragma unroll
        for (int j = 0; j < 4; j++) o[i][j] = 0.f;

    int st = 0;
    #pragma unroll 1
    for (int kc = 0; kc < 32; kc++) {
        const uint32_t uKh = sb + A_QTOT + st*A_STAGE;
        const uint32_t uKl = uKh + A_KARR;
        const uint32_t uVh = uKh + 2*A_KARR;
        const uint32_t uVl = uKh + 3*A_KARR;

        // S = Qn Kn^T over 64 keys
        float s[8][4];
        #pragma unroll
        for (int i = 0; i < 8; i++)
            #pragma unroll
            for (int j = 0; j < 4; j++) s[i][j] = 0.f;

        #pragma unroll
        for (int ks = 0; ks < 4; ks++) {
            uint32_t aQh[4], aQl[4];
            int qc = ks*2 + aChH;
            LDM4(aQh, sb + SWK(aRow, qc));
            LDM4(aQl, sb + A_QARR + SWK(aRow, qc));
            #pragma unroll
            for (int nt2 = 0; nt2 < 4; nt2++) {
                int r = bRowOff + nt2*16;
                int c = ks*2 + bChH;
                uint32_t rh[4], rl[4];
                LDM4(rh, uKh + SWK(r, c));
                LDM4(rl, uKl + SWK(r, c));
                uint32_t bh0[2] = {rh[0], rh[1]}, bh1[2] = {rh[2], rh[3]};
                uint32_t bl0[2] = {rl[0], rl[1]}, bl1[2] = {rl[2], rl[3]};
                const int nA = nt2*2, nB = nt2*2 + 1;
                MMA(s[nA], aQh, bh0); MMA(s[nB], aQh, bh1);
                MMA(s[nA], aQh, bl0); MMA(s[nB], aQh, bl1);
                MMA(s[nA], aQl, bh0); MMA(s[nB], aQl, bh1);
            }
        }

        // P = S^2 split-3, O += P V
        #pragma unroll
        for (int kt2 = 0; kt2 < 4; kt2++) {
            uint32_t aPh[4], aPl[4];
            {
                float x0, x1;
                x0 = s[2*kt2][0]*s[2*kt2][0];     x1 = s[2*kt2][1]*s[2*kt2][1];
                split2(x0, x1, aPh[0], aPl[0]);
                x0 = s[2*kt2][2]*s[2*kt2][2];     x1 = s[2*kt2][3]*s[2*kt2][3];
                split2(x0, x1, aPh[1], aPl[1]);
                x0 = s[2*kt2+1][0]*s[2*kt2+1][0]; x1 = s[2*kt2+1][1]*s[2*kt2+1][1];
                split2(x0, x1, aPh[2], aPl[2]);
                x0 = s[2*kt2+1][2]*s[2*kt2+1][2]; x1 = s[2*kt2+1][3]*s[2*kt2+1][3];
                split2(x0, x1, aPh[3], aPl[3]);
            }
            #pragma unroll
            for (int nt2 = 0; nt2 < 4; nt2++) {
                int r = bRowOff + nt2*16;
                int c = kt2*2 + bChH;
                uint32_t rh[4], rl[4];
                LDM4(rh, uVh + SWK(r, c));
                LDM4(rl, uVl + SWK(r, c));
                uint32_t bh0[2] = {rh[0], rh[1]}, bh1[2] = {rh[2], rh[3]};
                uint32_t bl0[2] = {rl[0], rl[1]}, bl1[2] = {rl[2], rl[3]};
                const int nA = nt2*2, nB = nt2*2 + 1;
                MMA(o[nA], aPh, bh0); MMA(o[nB], aPh, bh1);
                MMA(o[nA], aPh, bl0); MMA(o[nB], aPh, bl1);
                MMA(o[nA], aPl, bh0); MMA(o[nB], aPl, bh1);
            }
        }

        __syncthreads();
        if (kc + 2 < 32) {
            A_LOADKV((kc + 2) * 64, st);
            CPC();
            CPW(1);
            __syncthreads();
        } else if (kc + 1 < 32) {
            CPW(0);
            __syncthreads();
        }
        st ^= 1;
    }

    // ctx epilogue: split bf16, [b, s, DM]
    const int g = lane >> 2, tig = lane & 3;
    const int r0 = q0 + w*16 + g;
    const int b_ = bh >> 4, h_ = bh & 15;
    #pragma unroll
    for (int rr = 0; rr < 2; rr++) {
        const int s_ = r0 + rr*8;
        const size_t ob = ((size_t)b_ * SEQ + s_) * DM + h_ * DK;
        #pragma unroll
        for (int nt = 0; nt < 8; nt++) {
            uint32_t hp, lp;
            split2(o[nt][rr*2], o[nt][rr*2+1], hp, lp);
            *(uint32_t*)(ch + ob + nt*8 + tig*2) = hp;
            *(uint32_t*)(cl + ob + nt*8 + tig*2) = lp;
        }
    }
#undef A_LOADKV
}

// ---------------------------------------------------------------------------
extern "C" void kernel_launch(void* const* d_in, const int* in_sizes, int n_in,
                              void* d_out, int out_size)
{
    const float* Q    = (const float*)d_in[0];
    const float* K    = (const float*)d_in[1];
    const float* V    = (const float*)d_in[2];
    const float* Wq_w = (const float*)d_in[3];
    const float* Wq_b = (const float*)d_in[4];
    const float* Wk_w = (const float*)d_in[5];
    const float* Wk_b = (const float*)d_in[6];
    const float* Wv_w = (const float*)d_in[7];
    const float* Wv_b = (const float*)d_in[8];
    const float* Wo_w = (const float*)d_in[9];
    const float* Wo_b = (const float*)d_in[10];
    float* out = (float*)d_out;

    __nv_bfloat16* gb;
    cudaGetSymbolAddress((void**)&gb, g_buf);

    __nv_bfloat16* xh[3] = { gb + OFF_XQH, gb + OFF_XKH, gb + OFF_XVH };
    __nv_bfloat16* xl[3] = { gb + OFF_XQL, gb + OFF_XKL, gb + OFF_XVL };
    __nv_bfloat16* wh[4]; __nv_bfloat16* wl[4];
    for (int i = 0; i < 4; i++) { wh[i] = gb + OFF_W + (size_t)(2*i) * NW; wl[i] = wh[i] + NW; }
    __nv_bfloat16 *qh = gb + OFF_QH, *ql = gb + OFF_QL;
    __nv_bfloat16 *kh = gb + OFF_KH, *kl = gb + OFF_KL;
    __nv_bfloat16 *vh = gb + OFF_VH, *vl = gb + OFF_VL;
    __nv_bfloat16 *ch = gb + OFF_CH, *cl = gb + OFF_CL;

    cudaFuncSetAttribute(gemm_mma, cudaFuncAttributeMaxDynamicSharedMemorySize, GEMM_SMEM);
    cudaFuncSetAttribute(attn_mma, cudaFuncAttributeMaxDynamicSharedMemorySize, ATTN_SMEM);

    SplitArgs ia;
    ia.s[0] = (const float4*)Q; ia.s[1] = (const float4*)K; ia.s[2] = (const float4*)V;
    ia.s[3] = (const float4*)Q;
    for (int i = 0; i < 3; i++) { ia.h[i] = (uint4*)xh[i]; ia.l[i] = (uint4*)xl[i]; }
    ia.h[3] = (uint4*)xh[0]; ia.l[3] = (uint4*)xl[0];
    split_multi<<<dim3(NX/8/256, 3), 256>>>(ia, NX/8);

    SplitArgs wa;
    wa.s[0] = (const float4*)Wq_w; wa.s[1] = (const float4*)Wk_w;
    wa.s[2] = (const float4*)Wv_w; wa.s[3] = (const float4*)Wo_w;
    for (int i = 0; i < 4; i++) { wa.h[i] = (uint4*)wh[i]; wa.l[i] = (uint4*)wl[i]; }
    split_multi<<<dim3(NW/8/256, 4), 256>>>(wa, NW/8);

    dim3 ggrid(DM/128, MTOT/128);   // (8, 32)
    gemm_mma<<<ggrid, 256, GEMM_SMEM>>>(xh[0], xl[0], wh[0], wl[0], Wq_b, nullptr, qh, ql, 3);
    gemm_mma<<<ggrid, 256, GEMM_SMEM>>>(xh[1], xl[1], wh[1], wl[1], Wk_b, nullptr, kh, kl, 3);
    gemm_mma<<<ggrid, 256, GEMM_SMEM>>>(xh[2], xl[2], wh[2], wl[2], Wv_b, nullptr, vh, vl, 1);

    dim3 agrid(SEQ/128, NBH);       // (16, 32)
    attn_mma<<<agrid, 256, ATTN_SMEM>>>(qh, ql, kh, kl, vh, vl, ch, cl);

    gemm_mma<<<ggrid, 256, GEMM_SMEM>>>(ch, cl, wh[3], wl[3], Wo_b, out, nullptr, nullptr, 0);
}

// round 7
// speedup vs baseline: 3.7458x; 1.0028x over previous
#include <cuda_runtime.h>
#include <cuda_bf16.h>
#include <stdint.h>

#define DM 1024
#define NH 16
#define DK 64
#define SEQ 2048
#define MTOT 4096
#define NBH 32
#define NX (MTOT*DM)
#define NW (DM*DM)

// scratch arena
__device__ __nv_bfloat16 g_buf[14ull*NX + 8ull*NW];

#define OFF_XQH 0ull
#define OFF_XQL (1ull*NX)
#define OFF_XKH (2ull*NX)
#define OFF_XKL (3ull*NX)
#define OFF_XVH (4ull*NX)
#define OFF_XVL (5ull*NX)
#define OFF_W   (6ull*NX)
#define OFF_QH  (OFF_W + 8ull*NW)
#define OFF_QL  (OFF_QH + 1ull*NX)
#define OFF_KH  (OFF_QH + 2ull*NX)
#define OFF_KL  (OFF_QH + 3ull*NX)
#define OFF_VH  (OFF_QH + 4ull*NX)   /* transposed [b,h,d,s] */
#define OFF_VL  (OFF_QH + 5ull*NX)
#define OFF_CH  (OFF_QH + 6ull*NX)
#define OFF_CL  (OFF_QH + 7ull*NX)

static __device__ __forceinline__ uint32_t smem_u32(const void* p) {
    uint32_t a;
    asm("{ .reg .u64 t; cvta.to.shared.u64 t, %1; cvt.u32.u64 %0, t; }" : "=r"(a) : "l"(p));
    return a;
}

#define MMA(C, A, B) asm volatile( \
    "mma.sync.aligned.m16n8k16.row.col.f32.bf16.bf16.f32 " \
    "{%0,%1,%2,%3}, {%4,%5,%6,%7}, {%8,%9}, {%0,%1,%2,%3};" \
    : "+f"((C)[0]), "+f"((C)[1]), "+f"((C)[2]), "+f"((C)[3]) \
    : "r"((A)[0]), "r"((A)[1]), "r"((A)[2]), "r"((A)[3]), \
      "r"((B)[0]), "r"((B)[1]))

#define LDM4(R, ADDR) asm volatile( \
    "ldmatrix.sync.aligned.m8n8.x4.shared.b16 {%0,%1,%2,%3}, [%4];" \
    : "=r"((R)[0]), "=r"((R)[1]), "=r"((R)[2]), "=r"((R)[3]) : "r"(ADDR))

#define CP16(d, s) asm volatile("cp.async.cg.shared.global [%0], [%1], 16;" :: "r"(d), "l"(s))
#define CPC()   asm volatile("cp.async.commit_group;")
#define CPW(n)  asm volatile("cp.async.wait_group %0;" :: "n"(n))

// swizzles (byte offsets). SWC: 64B rows (4x16B chunks). SWK: 128B rows (8x16B chunks).
#define SWC(row, ch) (((row) << 6) + ((((ch) ^ (((row) >> 1) & 3))) << 4))
#define SWK(row, ch) (((row) << 7) + ((((ch) ^ ((row) & 7))) << 4))

static __device__ __forceinline__ void split2(float x0, float x1,
                                              uint32_t& hp, uint32_t& lp) {
    __nv_bfloat16 h0 = __float2bfloat16(x0), h1 = __float2bfloat16(x1);
    __nv_bfloat16 l0 = __float2bfloat16(x0 - __bfloat162float(h0));
    __nv_bfloat16 l1 = __float2bfloat16(x1 - __bfloat162float(h1));
    hp = (uint32_t)__bfloat16_as_ushort(h0) | ((uint32_t)__bfloat16_as_ushort(h1) << 16);
    lp = (uint32_t)__bfloat16_as_ushort(l0) | ((uint32_t)__bfloat16_as_ushort(l1) << 16);
}

// ---------------------------------------------------------------------------
struct SplitArgs {
    const float4* s[4];
    uint4* h[4];
    uint4* l[4];
};
__global__ void split_multi(SplitArgs a, int nchunks)
{
    const int y = blockIdx.y;
    const float4* src = a.s[y];
    uint4* hi = a.h[y];
    uint4* lo = a.l[y];
    int i = blockIdx.x * blockDim.x + threadIdx.x;
    if (i >= nchunks) return;
    float4 p = src[i*2], q = src[i*2+1];
    float v[8] = {p.x, p.y, p.z, p.w, q.x, q.y, q.z, q.w};
    uint4 H, L;
    split2(v[0], v[1], H.x, L.x);
    split2(v[2], v[3], H.y, L.y);
    split2(v[4], v[5], H.z, L.z);
    split2(v[6], v[7], H.w, L.w);
    hi[i] = H;
    lo[i] = L;
}

// ---------------------------------------------------------------------------
// GEMM: Y = A @ W^T + bias. CTA 256x128, k-step 32, 3-stage, single sync/iter.
// 8 warps, warp tile 64x64 (4 mt x 8 nt). bf16 split-3.
// ---------------------------------------------------------------------------
#define GA_OFF   0        /* Ah: 256 rows x 64B = 16384 */
#define GAL_OFF  16384    /* Al */
#define GB_OFF   32768    /* Bh: 128 rows x 64B = 8192 */
#define GBL_OFF  40960    /* Bl */
#define G_STAGE  49152
#define GEMM_SMEM (3*G_STAGE)   /* 147456 */
__global__ void __launch_bounds__(256, 1) gemm_mma(
    const __nv_bfloat16* __restrict__ Ah, const __nv_bfloat16* __restrict__ Al,
    const __nv_bfloat16* __restrict__ Wh, const __nv_bfloat16* __restrict__ Wl,
    const float* __restrict__ bias, float* __restrict__ Yf,
    __nv_bfloat16* __restrict__ Yh, __nv_bfloat16* __restrict__ Yl, int mode)
{
    extern __shared__ char sm[];
    const uint32_t sb = smem_u32(sm);
    const int t = threadIdx.x, lane = t & 31, w = t >> 5;
    const int wm = w & 3, wn = w >> 2;
    const int n0 = blockIdx.x * 128, m0 = blockIdx.y * 256;

    const __nv_bfloat16* aSrc[2] = { Ah + (size_t)m0 * DM, Al + (size_t)m0 * DM };
    const __nv_bfloat16* bSrc[2] = { Wh + (size_t)n0 * DM, Wl + (size_t)n0 * DM };

    const int lrow = t >> 2, lch = t & 3;

#define G_LOAD(kt, st) do { \
    _Pragma("unroll") \
    for (int p_ = 0; p_ < 2; p_++) { \
        uint32_t ab = sb + (st)*G_STAGE + p_*16384; \
        _Pragma("unroll") \
        for (int j_ = 0; j_ < 4; j_++) { \
            int r_ = lrow + j_*64; \
            CP16(ab + SWC(r_, lch), aSrc[p_] + (size_t)r_ * DM + (kt) + lch*8); \
        } \
        uint32_t bb = sb + (st)*G_STAGE + GB_OFF + p_*8192; \
        _Pragma("unroll") \
        for (int j_ = 0; j_ < 2; j_++) { \
            int r_ = lrow + j_*64; \
            CP16(bb + SWC(r_, lch), bSrc[p_] + (size_t)r_ * DM + (kt) + lch*8); \
        } \
    } \
} while (0)

    float acc[4][8][4];
    #pragma unroll
    for (int i = 0; i < 4; i++)
        #pragma unroll
        for (int j = 0; j < 8; j++)
            #pragma unroll
            for (int k = 0; k < 4; k++) acc[i][j][k] = 0.f;

    const int aRow0 = wm*64 + (lane & 15);
    const int aChH  = lane >> 4;
    const int bRowOff = wn*64 + (lane & 7) + ((lane >> 4) << 3);
    const int bChH  = (lane >> 3) & 1;

    G_LOAD(0, 0);  CPC();
    G_LOAD(32, 1); CPC();

    int st = 0;
    #pragma unroll 1
    for (int kc = 0; kc < 32; kc++) {
        CPW(1);
        __syncthreads();
        if (kc + 2 < 32) {
            int wr = st - 1 < 0 ? 2 : st - 1;
            G_LOAD((kc + 2) * 32, wr);
        }
        CPC();

        const uint32_t uAh = sb + st*G_STAGE;
        const uint32_t uAl = uAh + 16384;
        const uint32_t uBh = uAh + GB_OFF;
        const uint32_t uBl = uAh + GBL_OFF;

        #pragma unroll
        for (int ks = 0; ks < 2; ks++) {
            const int c = ks*2 + aChH;
            uint32_t aF[2][4][4];
            #pragma unroll
            for (int mt = 0; mt < 4; mt++) {
                LDM4(aF[0][mt], uAh + SWC(aRow0 + mt*16, c));
                LDM4(aF[1][mt], uAl + SWC(aRow0 + mt*16, c));
            }
            const int cb = ks*2 + bChH;
            #pragma unroll
            for (int nt2 = 0; nt2 < 4; nt2++) {
                int r = bRowOff + nt2*16;
                uint32_t rh[4], rl[4];
                LDM4(rh, uBh + SWC(r, cb));
                LDM4(rl, uBl + SWC(r, cb));
                uint32_t bh0[2] = {rh[0], rh[1]}, bh1[2] = {rh[2], rh[3]};
                uint32_t bl0[2] = {rl[0], rl[1]}, bl1[2] = {rl[2], rl[3]};
                const int nA = nt2*2, nB = nt2*2 + 1;
                #pragma unroll
                for (int mt = 0; mt < 4; mt++) {
                    MMA(acc[mt][nA], aF[0][mt], bh0);
                    MMA(acc[mt][nB], aF[0][mt], bh1);
                }
                #pragma unroll
                for (int mt = 0; mt < 4; mt++) {
                    MMA(acc[mt][nA], aF[0][mt], bl0);
                    MMA(acc[mt][nB], aF[0][mt], bl1);
                }
                #pragma unroll
                for (int mt = 0; mt < 4; mt++) {
                    MMA(acc[mt][nA], aF[1][mt], bh0);
                    MMA(acc[mt][nB], aF[1][mt], bh1);
                }
            }
        }
        st = st + 1 == 3 ? 0 : st + 1;
    }

    // ---- epilogue ----
    const int g = lane >> 2, tig = lane & 3;
    #pragma unroll
    for (int mt = 0; mt < 4; mt++) {
        const int r0 = m0 + wm*64 + mt*16 + g;
        float v[2][8][2];
        #pragma unroll
        for (int nt = 0; nt < 8; nt++) {
            int col = n0 + wn*64 + nt*8 + tig*2;
            float b0v = bias[col], b1v = bias[col + 1];
            v[0][nt][0] = acc[mt][nt][0] + b0v;
            v[0][nt][1] = acc[mt][nt][1] + b1v;
            v[1][nt][0] = acc[mt][nt][2] + b0v;
            v[1][nt][1] = acc[mt][nt][3] + b1v;
        }
        if (mode == 0) {
            #pragma unroll
            for (int rr = 0; rr < 2; rr++) {
                int r = r0 + rr*8;
                #pragma unroll
                for (int nt = 0; nt < 8; nt++) {
                    int col = n0 + wn*64 + nt*8 + tig*2;
                    *(float2*)(Yf + (size_t)r * DM + col) =
                        make_float2(v[rr][nt][0], v[rr][nt][1]);
                }
            }
        } else {
            if (mode == 3) {
                #pragma unroll
                for (int rr = 0; rr < 2; rr++) {
                    float ss = 0.f;
                    #pragma unroll
                    for (int nt = 0; nt < 8; nt++)
                        ss += v[rr][nt][0]*v[rr][nt][0] + v[rr][nt][1]*v[rr][nt][1];
                    ss += __shfl_xor_sync(0xffffffffu, ss, 1);
                    ss += __shfl_xor_sync(0xffffffffu, ss, 2);
                    float inv = rsqrtf(ss + 1e-8f);
                    #pragma unroll
                    for (int nt = 0; nt < 8; nt++) {
                        v[rr][nt][0] *= inv;
                        v[rr][nt][1] *= inv;
                    }
                }
            }
            const int h_ = (n0 >> 6) + wn;
            const int b_ = r0 >> 11;
            #pragma unroll
            for (int rr = 0; rr < 2; rr++) {
                const int s_ = (r0 + rr*8) & 2047;
                if (mode == 1) {
                    const size_t base = (size_t)(b_ * NH + h_) * DK;
                    #pragma unroll
                    for (int nt = 0; nt < 8; nt++) {
                        int d = nt*8 + tig*2;
                        float x0 = v[rr][nt][0], x1 = v[rr][nt][1];
                        __nv_bfloat16 h0 = __float2bfloat16(x0);
                        __nv_bfloat16 h1 = __float2bfloat16(x1);
                        Yh[(base + d    ) * SEQ + s_] = h0;
                        Yh[(base + d + 1) * SEQ + s_] = h1;
                        Yl[(base + d    ) * SEQ + s_] =
                            __float2bfloat16(x0 - __bfloat162float(h0));
                        Yl[(base + d + 1) * SEQ + s_] =
                            __float2bfloat16(x1 - __bfloat162float(h1));
                    }
                } else {
                    const size_t base = ((size_t)(b_ * NH + h_) * SEQ + s_) * DK;
                    #pragma unroll
                    for (int nt = 0; nt < 8; nt++) {
                        uint32_t hp, lp;
                        split2(v[rr][nt][0], v[rr][nt][1], hp, lp);
                        *(uint32_t*)(Yh + base + nt*8 + tig*2) = hp;
                        *(uint32_t*)(Yl + base + nt*8 + tig*2) = lp;
                    }
                }
            }
        }
    }
#undef G_LOAD
}

// ---------------------------------------------------------------------------
// Attention: CTA = (bh, 256-q tile), 8 warps x 32 q-rows, 64-key chunks,
// 3-stage cp.async, single sync per iter.
// ---------------------------------------------------------------------------
#define A_QARR  32768                 /* 256 rows x 128B */
#define A_KARR  8192                  /* 64 rows x 128B */
#define A_STAGE (4*A_KARR)            /* 32768: Kh Kl Vh Vl */
#define A_QTOT  (2*A_QARR)            /* 65536 */
#define ATTN_SMEM (A_QTOT + 3*A_STAGE)   /* 163840 */
__global__ void __launch_bounds__(256, 1) attn_mma(
    const __nv_bfloat16* __restrict__ qhp, const __nv_bfloat16* __restrict__ qlp,
    const __nv_bfloat16* __restrict__ khp, const __nv_bfloat16* __restrict__ klp,
    const __nv_bfloat16* __restrict__ vhp, const __nv_bfloat16* __restrict__ vlp,
    __nv_bfloat16* __restrict__ ch, __nv_bfloat16* __restrict__ cl)
{
    extern __shared__ char sm[];
    const uint32_t sb = smem_u32(sm);
    const int t = threadIdx.x, lane = t & 31, w = t >> 5;
    const int q0 = blockIdx.x * 256;
    const int bh = blockIdx.y;
    const size_t base = (size_t)bh * SEQ * DK;

    const __nv_bfloat16* Ksrc[2] = { khp + base, klp + base };
    const __nv_bfloat16* Vsrc[2] = { vhp + base, vlp + base };

    const int krow = t >> 2, kch = t & 3;

#define A_LOADKV(kt, st) do { \
    _Pragma("unroll") \
    for (int p_ = 0; p_ < 2; p_++) { \
        uint32_t kb = sb + A_QTOT + (st)*A_STAGE + p_*A_KARR; \
        CP16(kb + SWK(krow, kch),     Ksrc[p_] + (size_t)((kt) + krow) * DK + kch*8); \
        CP16(kb + SWK(krow, kch + 4), Ksrc[p_] + (size_t)((kt) + krow) * DK + (kch + 4)*8); \
        uint32_t vb = sb + A_QTOT + (st)*A_STAGE + (2+p_)*A_KARR; \
        CP16(vb + SWK(krow, kch),     Vsrc[p_] + (size_t)krow * SEQ + (kt) + kch*8); \
        CP16(vb + SWK(krow, kch + 4), Vsrc[p_] + (size_t)krow * SEQ + (kt) + (kch + 4)*8); \
    } \
} while (0)

    // Q loads: 256 rows x 8 chunks per part
    {
        const __nv_bfloat16* Qsrc[2] = { qhp + base, qlp + base };
        #pragma unroll
        for (int p_ = 0; p_ < 2; p_++)
            #pragma unroll
            for (int i = 0; i < 8; i++) {
                int c = t + i*256, row = c >> 3, chn = c & 7;
                CP16(sb + p_*A_QARR + SWK(row, chn),
                     Qsrc[p_] + (size_t)(q0 + row) * DK + chn*8);
            }
    }
    A_LOADKV(0, 0);  CPC();
    A_LOADKV(64, 1); CPC();

    const int aRow0 = w*32 + (lane & 15);
    const int aChH = lane >> 4;
    const int bRowOff = (lane & 7) + ((lane >> 4) << 3);
    const int bChH = (lane >> 3) & 1;

    float o[2][8][4];
    #pragma unroll
    for (int m = 0; m < 2; m++)
        #pragma unroll
        for (int i = 0; i < 8; i++)
            #pragma unroll
            for (int j = 0; j < 4; j++) o[m][i][j] = 0.f;

    int st = 0;
    #pragma unroll 1
    for (int kc = 0; kc < 32; kc++) {
        CPW(1);
        __syncthreads();
        if (kc + 2 < 32) {
            int wr = st - 1 < 0 ? 2 : st - 1;
            A_LOADKV((kc + 2) * 64, wr);
        }
        CPC();

        const uint32_t uKh = sb + A_QTOT + st*A_STAGE;
        const uint32_t uKl = uKh + A_KARR;
        const uint32_t uVh = uKh + 2*A_KARR;
        const uint32_t uVl = uKh + 3*A_KARR;

        // S = Qn Kn^T over 64 keys, 2 mt of 16 q-rows
        float s[2][8][4];
        #pragma unroll
        for (int m = 0; m < 2; m++)
            #pragma unroll
            for (int i = 0; i < 8; i++)
                #pragma unroll
                for (int j = 0; j < 4; j++) s[m][i][j] = 0.f;

        #pragma unroll
        for (int ks = 0; ks < 4; ks++) {
            const int qc = ks*2 + aChH;
            uint32_t aQ[2][2][4];   // [part][mt]
            #pragma unroll
            for (int mt = 0; mt < 2; mt++) {
                LDM4(aQ[0][mt], sb + SWK(aRow0 + mt*16, qc));
                LDM4(aQ[1][mt], sb + A_QARR + SWK(aRow0 + mt*16, qc));
            }
            const int cb = ks*2 + bChH;
            #pragma unroll
            for (int nt2 = 0; nt2 < 4; nt2++) {
                int r = bRowOff + nt2*16;
                uint32_t rh[4], rl[4];
                LDM4(rh, uKh + SWK(r, cb));
                LDM4(rl, uKl + SWK(r, cb));
                uint32_t bh0[2] = {rh[0], rh[1]}, bh1[2] = {rh[2], rh[3]};
                uint32_t bl0[2] = {rl[0], rl[1]}, bl1[2] = {rl[2], rl[3]};
                const int nA = nt2*2, nB = nt2*2 + 1;
                #pragma unroll
                for (int mt = 0; mt < 2; mt++) {
                    MMA(s[mt][nA], aQ[0][mt], bh0);
                    MMA(s[mt][nB], aQ[0][mt], bh1);
                }
                #pragma unroll
                for (int mt = 0; mt < 2; mt++) {
                    MMA(s[mt][nA], aQ[0][mt], bl0);
                    MMA(s[mt][nB], aQ[0][mt], bl1);
                }
                #pragma unroll
                for (int mt = 0; mt < 2; mt++) {
                    MMA(s[mt][nA], aQ[1][mt], bh0);
                    MMA(s[mt][nB], aQ[1][mt], bh1);
                }
            }
        }

        // P = S^2 split-3, O += P V
        #pragma unroll
        for (int kt2 = 0; kt2 < 4; kt2++) {
            uint32_t aPh[2][4], aPl[2][4];
            #pragma unroll
            for (int mt = 0; mt < 2; mt++) {
                float x0, x1;
                x0 = s[mt][2*kt2][0]*s[mt][2*kt2][0];     x1 = s[mt][2*kt2][1]*s[mt][2*kt2][1];
                split2(x0, x1, aPh[mt][0], aPl[mt][0]);
                x0 = s[mt][2*kt2][2]*s[mt][2*kt2][2];     x1 = s[mt][2*kt2][3]*s[mt][2*kt2][3];
                split2(x0, x1, aPh[mt][1], aPl[mt][1]);
                x0 = s[mt][2*kt2+1][0]*s[mt][2*kt2+1][0]; x1 = s[mt][2*kt2+1][1]*s[mt][2*kt2+1][1];
                split2(x0, x1, aPh[mt][2], aPl[mt][2]);
                x0 = s[mt][2*kt2+1][2]*s[mt][2*kt2+1][2]; x1 = s[mt][2*kt2+1][3]*s[mt][2*kt2+1][3];
                split2(x0, x1, aPh[mt][3], aPl[mt][3]);
            }
            const int cb = kt2*2 + bChH;
            #pragma unroll
            for (int nt2 = 0; nt2 < 4; nt2++) {
                int r = bRowOff + nt2*16;
                uint32_t rh[4], rl[4];
                LDM4(rh, uVh + SWK(r, cb));
                LDM4(rl, uVl + SWK(r, cb));
                uint32_t bh0[2] = {rh[0], rh[1]}, bh1[2] = {rh[2], rh[3]};
                uint32_t bl0[2] = {rl[0], rl[1]}, bl1[2] = {rl[2], rl[3]};
                const int nA = nt2*2, nB = nt2*2 + 1;
                #pragma unroll
                for (int mt = 0; mt < 2; mt++) {
                    MMA(o[mt][nA], aPh[mt], bh0);
                    MMA(o[mt][nB], aPh[mt], bh1);
                }
                #pragma unroll
                for (int mt = 0; mt < 2; mt++) {
                    MMA(o[mt][nA], aPh[mt], bl0);
                    MMA(o[mt][nB], aPh[mt], bl1);
                }
                #pragma unroll
                for (int mt = 0; mt < 2; mt++) {
                    MMA(o[mt][nA], aPl[mt], bh0);
                    MMA(o[mt][nB], aPl[mt], bh1);
                }
            }
        }
        st = st + 1 == 3 ? 0 : st + 1;
    }

    // ctx epilogue: split bf16, [b, s, DM]
    const int g = lane >> 2, tig = lane & 3;
    const int b_ = bh >> 4, h_ = bh & 15;
    #pragma unroll
    for (int mt = 0; mt < 2; mt++) {
        const int r0 = q0 + w*32 + mt*16 + g;
        #pragma unroll
        for (int rr = 0; rr < 2; rr++) {
            const int s_ = r0 + rr*8;
            const size_t ob = ((size_t)b_ * SEQ + s_) * DM + h_ * DK;
            #pragma unroll
            for (int nt = 0; nt < 8; nt++) {
                uint32_t hp, lp;
                split2(o[mt][nt][rr*2], o[mt][nt][rr*2+1], hp, lp);
                *(uint32_t*)(ch + ob + nt*8 + tig*2) = hp;
                *(uint32_t*)(cl + ob + nt*8 + tig*2) = lp;
            }
        }
    }
#undef A_LOADKV
}

// ---------------------------------------------------------------------------
extern "C" void kernel_launch(void* const* d_in, const int* in_sizes, int n_in,
                              void* d_out, int out_size)
{
    const float* Q    = (const float*)d_in[0];
    const float* K    = (const float*)d_in[1];
    const float* V    = (const float*)d_in[2];
    const float* Wq_w = (const float*)d_in[3];
    const float* Wq_b = (const float*)d_in[4];
    const float* Wk_w = (const float*)d_in[5];
    const float* Wk_b = (const float*)d_in[6];
    const float* Wv_w = (const float*)d_in[7];
    const float* Wv_b = (const float*)d_in[8];
    const float* Wo_w = (const float*)d_in[9];
    const float* Wo_b = (const float*)d_in[10];
    float* out = (float*)d_out;

    __nv_bfloat16* gb;
    cudaGetSymbolAddress((void**)&gb, g_buf);

    __nv_bfloat16* xh[3] = { gb + OFF_XQH, gb + OFF_XKH, gb + OFF_XVH };
    __nv_bfloat16* xl[3] = { gb + OFF_XQL, gb + OFF_XKL, gb + OFF_XVL };
    __nv_bfloat16* wh[4]; __nv_bfloat16* wl[4];
    for (int i = 0; i < 4; i++) { wh[i] = gb + OFF_W + (size_t)(2*i) * NW; wl[i] = wh[i] + NW; }
    __nv_bfloat16 *qh = gb + OFF_QH, *ql = gb + OFF_QL;
    __nv_bfloat16 *kh = gb + OFF_KH, *kl = gb + OFF_KL;
    __nv_bfloat16 *vh = gb + OFF_VH, *vl = gb + OFF_VL;
    __nv_bfloat16 *ch = gb + OFF_CH, *cl = gb + OFF_CL;

    cudaFuncSetAttribute(gemm_mma, cudaFuncAttributeMaxDynamicSharedMemorySize, GEMM_SMEM);
    cudaFuncSetAttribute(attn_mma, cudaFuncAttributeMaxDynamicSharedMemorySize, ATTN_SMEM);

    SplitArgs ia;
    ia.s[0] = (const float4*)Q; ia.s[1] = (const float4*)K; ia.s[2] = (const float4*)V;
    ia.s[3] = (const float4*)Q;
    for (int i = 0; i < 3; i++) { ia.h[i] = (uint4*)xh[i]; ia.l[i] = (uint4*)xl[i]; }
    ia.h[3] = (uint4*)xh[0]; ia.l[3] = (uint4*)xl[0];
    split_multi<<<dim3(NX/8/256, 3), 256>>>(ia, NX/8);

    SplitArgs wa;
    wa.s[0] = (const float4*)Wq_w; wa.s[1] = (const float4*)Wk_w;
    wa.s[2] = (const float4*)Wv_w; wa.s[3] = (const float4*)Wo_w;
    for (int i = 0; i < 4; i++) { wa.h[i] = (uint4*)wh[i]; wa.l[i] = (uint4*)wl[i]; }
    split_multi<<<dim3(NW/8/256, 4), 256>>>(wa, NW/8);

    dim3 ggrid(DM/128, MTOT/256);   // (8, 16) = 128 CTAs
    gemm_mma<<<ggrid, 256, GEMM_SMEM>>>(xh[0], xl[0], wh[0], wl[0], Wq_b, nullptr, qh, ql, 3);
    gemm_mma<<<ggrid, 256, GEMM_SMEM>>>(xh[1], xl[1], wh[1], wl[1], Wk_b, nullptr, kh, kl, 3);
    gemm_mma<<<ggrid, 256, GEMM_SMEM>>>(xh[2], xl[2], wh[2], wl[2], Wv_b, nullptr, vh, vl, 1);

    dim3 agrid(SEQ/256, NBH);       // (8, 32) = 256 CTAs
    attn_mma<<<agrid, 256, ATTN_SMEM>>>(qh, ql, kh, kl, vh, vl, ch, cl);

    gemm_mma<<<ggrid, 256, GEMM_SMEM>>>(ch, cl, wh[3], wl[3], Wo_b, out, nullptr, nullptr, 0);
}

// round 8
// speedup vs baseline: 3.7974x; 1.0138x over previous
#include <cuda_runtime.h>
#include <cuda_bf16.h>
#include <stdint.h>

#define DM 1024
#define NH 16
#define DK 64
#define SEQ 2048
#define MTOT 4096
#define NBH 32
#define NX (MTOT*DM)
#define NW (DM*DM)

// scratch arena
__device__ __nv_bfloat16 g_buf[14ull*NX + 8ull*NW];

#define OFF_XQH 0ull
#define OFF_XQL (1ull*NX)
#define OFF_XKH (2ull*NX)
#define OFF_XKL (3ull*NX)
#define OFF_XVH (4ull*NX)
#define OFF_XVL (5ull*NX)
#define OFF_W   (6ull*NX)
#define OFF_QH  (OFF_W + 8ull*NW)
#define OFF_QL  (OFF_QH + 1ull*NX)
#define OFF_KH  (OFF_QH + 2ull*NX)
#define OFF_KL  (OFF_QH + 3ull*NX)
#define OFF_VH  (OFF_QH + 4ull*NX)   /* transposed [b,h,d,s] */
#define OFF_VL  (OFF_QH + 5ull*NX)
#define OFF_CH  (OFF_QH + 6ull*NX)
#define OFF_CL  (OFF_QH + 7ull*NX)

static __device__ __forceinline__ uint32_t smem_u32(const void* p) {
    uint32_t a;
    asm("{ .reg .u64 t; cvta.to.shared.u64 t, %1; cvt.u32.u64 %0, t; }" : "=r"(a) : "l"(p));
    return a;
}

#define MMA(C, A, B) asm volatile( \
    "mma.sync.aligned.m16n8k16.row.col.f32.bf16.bf16.f32 " \
    "{%0,%1,%2,%3}, {%4,%5,%6,%7}, {%8,%9}, {%0,%1,%2,%3};" \
    : "+f"((C)[0]), "+f"((C)[1]), "+f"((C)[2]), "+f"((C)[3]) \
    : "r"((A)[0]), "r"((A)[1]), "r"((A)[2]), "r"((A)[3]), \
      "r"((B)[0]), "r"((B)[1]))

#define LDM4(R, ADDR) asm volatile( \
    "ldmatrix.sync.aligned.m8n8.x4.shared.b16 {%0,%1,%2,%3}, [%4];" \
    : "=r"((R)[0]), "=r"((R)[1]), "=r"((R)[2]), "=r"((R)[3]) : "r"(ADDR))

#define CP16(d, s) asm volatile("cp.async.cg.shared.global [%0], [%1], 16;" :: "r"(d), "l"(s))
#define CPC()   asm volatile("cp.async.commit_group;")
#define CPW(n)  asm volatile("cp.async.wait_group %0;" :: "n"(n))

// swizzles (byte offsets). SWC: 64B rows (4x16B chunks). SWK: 128B rows (8x16B chunks).
#define SWC(row, ch) (((row) << 6) + ((((ch) ^ (((row) >> 1) & 3))) << 4))
#define SWK(row, ch) (((row) << 7) + ((((ch) ^ ((row) & 7))) << 4))

static __device__ __forceinline__ void split2(float x0, float x1,
                                              uint32_t& hp, uint32_t& lp) {
    __nv_bfloat16 h0 = __float2bfloat16(x0), h1 = __float2bfloat16(x1);
    __nv_bfloat16 l0 = __float2bfloat16(x0 - __bfloat162float(h0));
    __nv_bfloat16 l1 = __float2bfloat16(x1 - __bfloat162float(h1));
    hp = (uint32_t)__bfloat16_as_ushort(h0) | ((uint32_t)__bfloat16_as_ushort(h1) << 16);
    lp = (uint32_t)__bfloat16_as_ushort(l0) | ((uint32_t)__bfloat16_as_ushort(l1) << 16);
}

// ---------------------------------------------------------------------------
struct SplitArgs {
    const float4* s[4];
    uint4* h[4];
    uint4* l[4];
};
__global__ void split_multi(SplitArgs a, int nchunks)
{
    const int y = blockIdx.y;
    const float4* src = a.s[y];
    uint4* hi = a.h[y];
    uint4* lo = a.l[y];
    int i = blockIdx.x * blockDim.x + threadIdx.x;
    if (i >= nchunks) return;
    float4 p = src[i*2], q = src[i*2+1];
    float v[8] = {p.x, p.y, p.z, p.w, q.x, q.y, q.z, q.w};
    uint4 H, L;
    split2(v[0], v[1], H.x, L.x);
    split2(v[2], v[3], H.y, L.y);
    split2(v[4], v[5], H.z, L.z);
    split2(v[6], v[7], H.w, L.w);
    hi[i] = H;
    lo[i] = L;
}

// ---------------------------------------------------------------------------
// Batched GEMM: Y = A @ W^T + bias, gridDim.z selects the problem.
// CTA 256x128, k-step 64 (two 32-k sub-blocks), 2-stage, 1 sync/iter.
// 8 warps, warp tile 64x64. bf16 split-3.
// ---------------------------------------------------------------------------
struct GemmArgs {
    const __nv_bfloat16* ah[3];
    const __nv_bfloat16* al[3];
    const __nv_bfloat16* wh[3];
    const __nv_bfloat16* wl[3];
    const float* bias[3];
    float* yf[3];
    __nv_bfloat16* yh[3];
    __nv_bfloat16* yl[3];
    int mode[3];
};
#define G_SUB    49152    /* per 32-k sub-block: A 32KB + B 16KB */
#define G_STAGE  98304
#define GEMM_SMEM (2*G_STAGE)   /* 196608 */
__global__ void __launch_bounds__(256, 1) gemm_mma(GemmArgs ga)
{
    extern __shared__ char sm[];
    const uint32_t sb = smem_u32(sm);
    const int z = blockIdx.z;
    const int t = threadIdx.x, lane = t & 31, w = t >> 5;
    const int wm = w & 3, wn = w >> 2;
    const int n0 = blockIdx.x * 128, m0 = blockIdx.y * 256;
    const int mode = ga.mode[z];
    const float* bias = ga.bias[z];

    const __nv_bfloat16* aSrc[2] = { ga.ah[z] + (size_t)m0 * DM, ga.al[z] + (size_t)m0 * DM };
    const __nv_bfloat16* bSrc[2] = { ga.wh[z] + (size_t)n0 * DM, ga.wl[z] + (size_t)n0 * DM };

    const int lrow = t >> 2, lch = t & 3;

#define G_LOAD(kt, st) do { \
    _Pragma("unroll") \
    for (int s_2 = 0; s_2 < 2; s_2++) { \
        _Pragma("unroll") \
        for (int p_ = 0; p_ < 2; p_++) { \
            uint32_t ab = sb + (st)*G_STAGE + s_2*G_SUB + p_*16384; \
            _Pragma("unroll") \
            for (int j_ = 0; j_ < 4; j_++) { \
                int r_ = lrow + j_*64; \
                CP16(ab + SWC(r_, lch), aSrc[p_] + (size_t)r_ * DM + (kt) + s_2*32 + lch*8); \
            } \
            uint32_t bb = sb + (st)*G_STAGE + s_2*G_SUB + 32768 + p_*8192; \
            _Pragma("unroll") \
            for (int j_ = 0; j_ < 2; j_++) { \
                int r_ = lrow + j_*64; \
                CP16(bb + SWC(r_, lch), bSrc[p_] + (size_t)r_ * DM + (kt) + s_2*32 + lch*8); \
            } \
        } \
    } \
} while (0)

    float acc[4][8][4];
    #pragma unroll
    for (int i = 0; i < 4; i++)
        #pragma unroll
        for (int j = 0; j < 8; j++)
            #pragma unroll
            for (int k = 0; k < 4; k++) acc[i][j][k] = 0.f;

    const int aRow0 = wm*64 + (lane & 15);
    const int aChH  = lane >> 4;
    const int bRowOff = wn*64 + (lane & 7) + ((lane >> 4) << 3);
    const int bChH  = (lane >> 3) & 1;

    G_LOAD(0, 0);  CPC();

    #pragma unroll 1
    for (int kc = 0; kc < 16; kc++) {
        const int st = kc & 1;
        CPW(0);
        __syncthreads();
        if (kc + 1 < 16) G_LOAD((kc + 1) * 64, st ^ 1);
        CPC();

        #pragma unroll
        for (int sub = 0; sub < 2; sub++) {
            const uint32_t uAh = sb + st*G_STAGE + sub*G_SUB;
            const uint32_t uAl = uAh + 16384;
            const uint32_t uBh = uAh + 32768;
            const uint32_t uBl = uAh + 40960;
            #pragma unroll
            for (int ks = 0; ks < 2; ks++) {
                const int c = ks*2 + aChH;
                uint32_t aF[2][4][4];
                #pragma unroll
                for (int mt = 0; mt < 4; mt++) {
                    LDM4(aF[0][mt], uAh + SWC(aRow0 + mt*16, c));
                    LDM4(aF[1][mt], uAl + SWC(aRow0 + mt*16, c));
                }
                const int cb = ks*2 + bChH;
                #pragma unroll
                for (int nt2 = 0; nt2 < 4; nt2++) {
                    int r = bRowOff + nt2*16;
                    uint32_t rh[4], rl[4];
                    LDM4(rh, uBh + SWC(r, cb));
                    LDM4(rl, uBl + SWC(r, cb));
                    uint32_t bh0[2] = {rh[0], rh[1]}, bh1[2] = {rh[2], rh[3]};
                    uint32_t bl0[2] = {rl[0], rl[1]}, bl1[2] = {rl[2], rl[3]};
                    const int nA = nt2*2, nB = nt2*2 + 1;
                    #pragma unroll
                    for (int mt = 0; mt < 4; mt++) {
                        MMA(acc[mt][nA], aF[0][mt], bh0);
                        MMA(acc[mt][nB], aF[0][mt], bh1);
                    }
                    #pragma unroll
                    for (int mt = 0; mt < 4; mt++) {
                        MMA(acc[mt][nA], aF[0][mt], bl0);
                        MMA(acc[mt][nB], aF[0][mt], bl1);
                    }
                    #pragma unroll
                    for (int mt = 0; mt < 4; mt++) {
                        MMA(acc[mt][nA], aF[1][mt], bh0);
                        MMA(acc[mt][nB], aF[1][mt], bh1);
                    }
                }
            }
        }
    }

    // ---- epilogue ----
    float* Yf = ga.yf[z];
    __nv_bfloat16* Yh = ga.yh[z];
    __nv_bfloat16* Yl = ga.yl[z];
    const int g = lane >> 2, tig = lane & 3;
    #pragma unroll
    for (int mt = 0; mt < 4; mt++) {
        const int r0 = m0 + wm*64 + mt*16 + g;
        float v[2][8][2];
        #pragma unroll
        for (int nt = 0; nt < 8; nt++) {
            int col = n0 + wn*64 + nt*8 + tig*2;
            float b0v = bias[col], b1v = bias[col + 1];
            v[0][nt][0] = acc[mt][nt][0] + b0v;
            v[0][nt][1] = acc[mt][nt][1] + b1v;
            v[1][nt][0] = acc[mt][nt][2] + b0v;
            v[1][nt][1] = acc[mt][nt][3] + b1v;
        }
        if (mode == 0) {
            #pragma unroll
            for (int rr = 0; rr < 2; rr++) {
                int r = r0 + rr*8;
                #pragma unroll
                for (int nt = 0; nt < 8; nt++) {
                    int col = n0 + wn*64 + nt*8 + tig*2;
                    *(float2*)(Yf + (size_t)r * DM + col) =
                        make_float2(v[rr][nt][0], v[rr][nt][1]);
                }
            }
        } else {
            if (mode == 3) {
                #pragma unroll
                for (int rr = 0; rr < 2; rr++) {
                    float ss = 0.f;
                    #pragma unroll
                    for (int nt = 0; nt < 8; nt++)
                        ss += v[rr][nt][0]*v[rr][nt][0] + v[rr][nt][1]*v[rr][nt][1];
                    ss += __shfl_xor_sync(0xffffffffu, ss, 1);
                    ss += __shfl_xor_sync(0xffffffffu, ss, 2);
                    float inv = rsqrtf(ss + 1e-8f);
                    #pragma unroll
                    for (int nt = 0; nt < 8; nt++) {
                        v[rr][nt][0] *= inv;
                        v[rr][nt][1] *= inv;
                    }
                }
            }
            const int h_ = (n0 >> 6) + wn;
            const int b_ = r0 >> 11;
            #pragma unroll
            for (int rr = 0; rr < 2; rr++) {
                const int s_ = (r0 + rr*8) & 2047;
                if (mode == 1) {
                    const size_t base = (size_t)(b_ * NH + h_) * DK;
                    #pragma unroll
                    for (int nt = 0; nt < 8; nt++) {
                        int d = nt*8 + tig*2;
                        float x0 = v[rr][nt][0], x1 = v[rr][nt][1];
                        __nv_bfloat16 h0 = __float2bfloat16(x0);
                        __nv_bfloat16 h1 = __float2bfloat16(x1);
                        Yh[(base + d    ) * SEQ + s_] = h0;
                        Yh[(base + d + 1) * SEQ + s_] = h1;
                        Yl[(base + d    ) * SEQ + s_] =
                            __float2bfloat16(x0 - __bfloat162float(h0));
                        Yl[(base + d + 1) * SEQ + s_] =
                            __float2bfloat16(x1 - __bfloat162float(h1));
                    }
                } else {
                    const size_t base = ((size_t)(b_ * NH + h_) * SEQ + s_) * DK;
                    #pragma unroll
                    for (int nt = 0; nt < 8; nt++) {
                        uint32_t hp, lp;
                        split2(v[rr][nt][0], v[rr][nt][1], hp, lp);
                        *(uint32_t*)(Yh + base + nt*8 + tig*2) = hp;
                        *(uint32_t*)(Yl + base + nt*8 + tig*2) = lp;
                    }
                }
            }
        }
    }
#undef G_LOAD
}

// ---------------------------------------------------------------------------
// Attention: CTA = (bh, 256-q tile), 8 warps x 32 q-rows.
// 128 keys per iteration (two 64-key sub-chunks), 2-stage, 1 sync/iter.
// ---------------------------------------------------------------------------
#define A_QARR  32768                 /* 256 rows x 128B */
#define A_KARR  8192                  /* 64 rows x 128B per part */
#define A_STAGE 65536                 /* K(sub0,sub1) + V(sub0,sub1), 2 parts each */
#define A_QTOT  (2*A_QARR)            /* 65536 */
#define ATTN_SMEM (A_QTOT + 2*A_STAGE)   /* 196608 */
__global__ void __launch_bounds__(256, 1) attn_mma(
    const __nv_bfloat16* __restrict__ qhp, const __nv_bfloat16* __restrict__ qlp,
    const __nv_bfloat16* __restrict__ khp, const __nv_bfloat16* __restrict__ klp,
    const __nv_bfloat16* __restrict__ vhp, const __nv_bfloat16* __restrict__ vlp,
    __nv_bfloat16* __restrict__ ch, __nv_bfloat16* __restrict__ cl)
{
    extern __shared__ char sm[];
    const uint32_t sb = smem_u32(sm);
    const int t = threadIdx.x, lane = t & 31, w = t >> 5;
    const int q0 = blockIdx.x * 256;
    const int bh = blockIdx.y;
    const size_t base = (size_t)bh * SEQ * DK;

    const __nv_bfloat16* Ksrc[2] = { khp + base, klp + base };
    const __nv_bfloat16* Vsrc[2] = { vhp + base, vlp + base };

    const int krow = t >> 2, kch = t & 3;

    // stage layout: sub*16384 + part*8192 for K ; 32768 + sub*16384 + part*8192 for V
#define A_LOADKV(kt, st) do { \
    _Pragma("unroll") \
    for (int s_2 = 0; s_2 < 2; s_2++) { \
        _Pragma("unroll") \
        for (int p_ = 0; p_ < 2; p_++) { \
            uint32_t kb = sb + A_QTOT + (st)*A_STAGE + s_2*16384 + p_*A_KARR; \
            CP16(kb + SWK(krow, kch),     Ksrc[p_] + (size_t)((kt) + s_2*64 + krow) * DK + kch*8); \
            CP16(kb + SWK(krow, kch + 4), Ksrc[p_] + (size_t)((kt) + s_2*64 + krow) * DK + (kch + 4)*8); \
            uint32_t vb = sb + A_QTOT + (st)*A_STAGE + 32768 + s_2*16384 + p_*A_KARR; \
            CP16(vb + SWK(krow, kch),     Vsrc[p_] + (size_t)krow * SEQ + (kt) + s_2*64 + kch*8); \
            CP16(vb + SWK(krow, kch + 4), Vsrc[p_] + (size_t)krow * SEQ + (kt) + s_2*64 + (kch + 4)*8); \
        } \
    } \
} while (0)

    // Q loads: 256 rows x 8 chunks per part
    {
        const __nv_bfloat16* Qsrc[2] = { qhp + base, qlp + base };
        #pragma unroll
        for (int p_ = 0; p_ < 2; p_++)
            #pragma unroll
            for (int i = 0; i < 8; i++) {
                int c = t + i*256, row = c >> 3, chn = c & 7;
                CP16(sb + p_*A_QARR + SWK(row, chn),
                     Qsrc[p_] + (size_t)(q0 + row) * DK + chn*8);
            }
    }
    A_LOADKV(0, 0);  CPC();

    const int aRow0 = w*32 + (lane & 15);
    const int aChH = lane >> 4;
    const int bRowOff = (lane & 7) + ((lane >> 4) << 3);
    const int bChH = (lane >> 3) & 1;

    float o[2][8][4];
    #pragma unroll
    for (int m = 0; m < 2; m++)
        #pragma unroll
        for (int i = 0; i < 8; i++)
            #pragma unroll
            for (int j = 0; j < 4; j++) o[m][i][j] = 0.f;

    #pragma unroll 1
    for (int kc = 0; kc < 16; kc++) {
        const int st = kc & 1;
        CPW(0);
        __syncthreads();
        if (kc + 1 < 16) A_LOADKV((kc + 1) * 128, st ^ 1);
        CPC();

        #pragma unroll
        for (int sub = 0; sub < 2; sub++) {
            const uint32_t uKh = sb + A_QTOT + st*A_STAGE + sub*16384;
            const uint32_t uKl = uKh + A_KARR;
            const uint32_t uVh = sb + A_QTOT + st*A_STAGE + 32768 + sub*16384;
            const uint32_t uVl = uVh + A_KARR;

            // S = Qn Kn^T over 64 keys, 2 mt of 16 q-rows
            float s[2][8][4];
            #pragma unroll
            for (int m = 0; m < 2; m++)
                #pragma unroll
                for (int i = 0; i < 8; i++)
                    #pragma unroll
                    for (int j = 0; j < 4; j++) s[m][i][j] = 0.f;

            #pragma unroll
            for (int ks = 0; ks < 4; ks++) {
                const int qc = ks*2 + aChH;
                uint32_t aQ[2][2][4];
                #pragma unroll
                for (int mt = 0; mt < 2; mt++) {
                    LDM4(aQ[0][mt], sb + SWK(aRow0 + mt*16, qc));
                    LDM4(aQ[1][mt], sb + A_QARR + SWK(aRow0 + mt*16, qc));
                }
                const int cb = ks*2 + bChH;
                #pragma unroll
                for (int nt2 = 0; nt2 < 4; nt2++) {
                    int r = bRowOff + nt2*16;
                    uint32_t rh[4], rl[4];
                    LDM4(rh, uKh + SWK(r, cb));
                    LDM4(rl, uKl + SWK(r, cb));
                    uint32_t bh0[2] = {rh[0], rh[1]}, bh1[2] = {rh[2], rh[3]};
                    uint32_t bl0[2] = {rl[0], rl[1]}, bl1[2] = {rl[2], rl[3]};
                    const int nA = nt2*2, nB = nt2*2 + 1;
                    #pragma unroll
                    for (int mt = 0; mt < 2; mt++) {
                        MMA(s[mt][nA], aQ[0][mt], bh0);
                        MMA(s[mt][nB], aQ[0][mt], bh1);
                    }
                    #pragma unroll
                    for (int mt = 0; mt < 2; mt++) {
                        MMA(s[mt][nA], aQ[0][mt], bl0);
                        MMA(s[mt][nB], aQ[0][mt], bl1);
                    }
                    #pragma unroll
                    for (int mt = 0; mt < 2; mt++) {
                        MMA(s[mt][nA], aQ[1][mt], bh0);
                        MMA(s[mt][nB], aQ[1][mt], bh1);
                    }
                }
            }

            // P = S^2 split-3, O += P V
            #pragma unroll
            for (int kt2 = 0; kt2 < 4; kt2++) {
                uint32_t aPh[2][4], aPl[2][4];
                #pragma unroll
                for (int mt = 0; mt < 2; mt++) {
                    float x0, x1;
                    x0 = s[mt][2*kt2][0]*s[mt][2*kt2][0];     x1 = s[mt][2*kt2][1]*s[mt][2*kt2][1];
                    split2(x0, x1, aPh[mt][0], aPl[mt][0]);
                    x0 = s[mt][2*kt2][2]*s[mt][2*kt2][2];     x1 = s[mt][2*kt2][3]*s[mt][2*kt2][3];
                    split2(x0, x1, aPh[mt][1], aPl[mt][1]);
                    x0 = s[mt][2*kt2+1][0]*s[mt][2*kt2+1][0]; x1 = s[mt][2*kt2+1][1]*s[mt][2*kt2+1][1];
                    split2(x0, x1, aPh[mt][2], aPl[mt][2]);
                    x0 = s[mt][2*kt2+1][2]*s[mt][2*kt2+1][2]; x1 = s[mt][2*kt2+1][3]*s[mt][2*kt2+1][3];
                    split2(x0, x1, aPh[mt][3], aPl[mt][3]);
                }
                const int cb = kt2*2 + bChH;
                #pragma unroll
                for (int nt2 = 0; nt2 < 4; nt2++) {
                    int r = bRowOff + nt2*16;
                    uint32_t rh[4], rl[4];
                    LDM4(rh, uVh + SWK(r, cb));
                    LDM4(rl, uVl + SWK(r, cb));
                    uint32_t bh0[2] = {rh[0], rh[1]}, bh1[2] = {rh[2], rh[3]};
                    uint32_t bl0[2] = {rl[0], rl[1]}, bl1[2] = {rl[2], rl[3]};
                    const int nA = nt2*2, nB = nt2*2 + 1;
                    #pragma unroll
                    for (int mt = 0; mt < 2; mt++) {
                        MMA(o[mt][nA], aPh[mt], bh0);
                        MMA(o[mt][nB], aPh[mt], bh1);
                    }
                    #pragma unroll
                    for (int mt = 0; mt < 2; mt++) {
                        MMA(o[mt][nA], aPh[mt], bl0);
                        MMA(o[mt][nB], aPh[mt], bl1);
                    }
                    #pragma unroll
                    for (int mt = 0; mt < 2; mt++) {
                        MMA(o[mt][nA], aPl[mt], bh0);
                        MMA(o[mt][nB], aPl[mt], bh1);
                    }
                }
            }
        }
    }

    // ctx epilogue: split bf16, [b, s, DM]
    const int g = lane >> 2, tig = lane & 3;
    const int b_ = bh >> 4, h_ = bh & 15;
    #pragma unroll
    for (int mt = 0; mt < 2; mt++) {
        const int r0 = q0 + w*32 + mt*16 + g;
        #pragma unroll
        for (int rr = 0; rr < 2; rr++) {
            const int s_ = r0 + rr*8;
            const size_t ob = ((size_t)b_ * SEQ + s_) * DM + h_ * DK;
            #pragma unroll
            for (int nt = 0; nt < 8; nt++) {
                uint32_t hp, lp;
                split2(o[mt][nt][rr*2], o[mt][nt][rr*2+1], hp, lp);
                *(uint32_t*)(ch + ob + nt*8 + tig*2) = hp;
                *(uint32_t*)(cl + ob + nt*8 + tig*2) = lp;
            }
        }
    }
#undef A_LOADKV
}

// ---------------------------------------------------------------------------
extern "C" void kernel_launch(void* const* d_in, const int* in_sizes, int n_in,
                              void* d_out, int out_size)
{
    const float* Q    = (const float*)d_in[0];
    const float* K    = (const float*)d_in[1];
    const float* V    = (const float*)d_in[2];
    const float* Wq_w = (const float*)d_in[3];
    const float* Wq_b = (const float*)d_in[4];
    const float* Wk_w = (const float*)d_in[5];
    const float* Wk_b = (const float*)d_in[6];
    const float* Wv_w = (const float*)d_in[7];
    const float* Wv_b = (const float*)d_in[8];
    const float* Wo_w = (const float*)d_in[9];
    const float* Wo_b = (const float*)d_in[10];
    float* out = (float*)d_out;

    __nv_bfloat16* gb;
    cudaGetSymbolAddress((void**)&gb, g_buf);

    __nv_bfloat16* xh[3] = { gb + OFF_XQH, gb + OFF_XKH, gb + OFF_XVH };
    __nv_bfloat16* xl[3] = { gb + OFF_XQL, gb + OFF_XKL, gb + OFF_XVL };
    __nv_bfloat16* wh[4]; __nv_bfloat16* wl[4];
    for (int i = 0; i < 4; i++) { wh[i] = gb + OFF_W + (size_t)(2*i) * NW; wl[i] = wh[i] + NW; }
    __nv_bfloat16 *qh = gb + OFF_QH, *ql = gb + OFF_QL;
    __nv_bfloat16 *kh = gb + OFF_KH, *kl = gb + OFF_KL;
    __nv_bfloat16 *vh = gb + OFF_VH, *vl = gb + OFF_VL;
    __nv_bfloat16 *ch = gb + OFF_CH, *cl = gb + OFF_CL;

    cudaFuncSetAttribute(gemm_mma, cudaFuncAttributeMaxDynamicSharedMemorySize, GEMM_SMEM);
    cudaFuncSetAttribute(attn_mma, cudaFuncAttributeMaxDynamicSharedMemorySize, ATTN_SMEM);

    SplitArgs ia;
    ia.s[0] = (const float4*)Q; ia.s[1] = (const float4*)K; ia.s[2] = (const float4*)V;
    ia.s[3] = (const float4*)Q;
    for (int i = 0; i < 3; i++) { ia.h[i] = (uint4*)xh[i]; ia.l[i] = (uint4*)xl[i]; }
    ia.h[3] = (uint4*)xh[0]; ia.l[3] = (uint4*)xl[0];
    split_multi<<<dim3(NX/8/256, 3), 256>>>(ia, NX/8);

    SplitArgs wa;
    wa.s[0] = (const float4*)Wq_w; wa.s[1] = (const float4*)Wk_w;
    wa.s[2] = (const float4*)Wv_w; wa.s[3] = (const float4*)Wo_w;
    for (int i = 0; i < 4; i++) { wa.h[i] = (uint4*)wh[i]; wa.l[i] = (uint4*)wl[i]; }
    split_multi<<<dim3(NW/8/256, 4), 256>>>(wa, NW/8);

    // batched Q/K/V projections: gridDim.z = 3
    GemmArgs gqkv;
    gqkv.ah[0] = xh[0]; gqkv.al[0] = xl[0]; gqkv.wh[0] = wh[0]; gqkv.wl[0] = wl[0];
    gqkv.bias[0] = Wq_b; gqkv.yf[0] = nullptr; gqkv.yh[0] = qh; gqkv.yl[0] = ql; gqkv.mode[0] = 3;
    gqkv.ah[1] = xh[1]; gqkv.al[1] = xl[1]; gqkv.wh[1] = wh[1]; gqkv.wl[1] = wl[1];
    gqkv.bias[1] = Wk_b; gqkv.yf[1] = nullptr; gqkv.yh[1] = kh; gqkv.yl[1] = kl; gqkv.mode[1] = 3;
    gqkv.ah[2] = xh[2]; gqkv.al[2] = xl[2]; gqkv.wh[2] = wh[2]; gqkv.wl[2] = wl[2];
    gqkv.bias[2] = Wv_b; gqkv.yf[2] = nullptr; gqkv.yh[2] = vh; gqkv.yl[2] = vl; gqkv.mode[2] = 1;
    gemm_mma<<<dim3(DM/128, MTOT/256, 3), 256, GEMM_SMEM>>>(gqkv);

    dim3 agrid(SEQ/256, NBH);       // (8, 32) = 256 CTAs
    attn_mma<<<agrid, 256, ATTN_SMEM>>>(qh, ql, kh, kl, vh, vl, ch, cl);

    GemmArgs go;
    go.ah[0] = ch; go.al[0] = cl; go.wh[0] = wh[3]; go.wl[0] = wl[3];
    go.bias[0] = Wo_b; go.yf[0] = out; go.yh[0] = nullptr; go.yl[0] = nullptr; go.mode[0] = 0;
    go.ah[1] = go.ah[0]; go.al[1] = go.al[0]; go.wh[1] = go.wh[0]; go.wl[1] = go.wl[0];
    go.bias[1] = go.bias[0]; go.yf[1] = go.yf[0]; go.yh[1] = nullptr; go.yl[1] = nullptr; go.mode[1] = 0;
    go.ah[2] = go.ah[0]; go.al[2] = go.al[0]; go.wh[2] = go.wh[0]; go.wl[2] = go.wl[0];
    go.bias[2] = go.bias[0]; go.yf[2] = go.yf[0]; go.yh[2] = nullptr; go.yl[2] = nullptr; go.mode[2] = 0;
    gemm_mma<<<dim3(DM/128, MTOT/256, 1), 256, GEMM_SMEM>>>(go);
}